// round 10
// baseline (speedup 1.0000x reference)
#include <cuda_runtime.h>
#include <cuda_bf16.h>
#include <cstdint>

#define B_    1024
#define T_    256
#define D_    64
#define H_    128
#define GC    384

__device__ float g_xproj[(size_t)B_ * T_ * GC];
__device__ int   g_order[B_];

__device__ __forceinline__ float sigmoidf_(float x) {
    return __fdividef(1.0f, 1.0f + __expf(-x));
}
__device__ __forceinline__ float tanhf_(float x) {
    return 1.0f - __fdividef(2.0f, __expf(2.0f * x) + 1.0f);
}

// ---------------- warp-level bf16 MMA ----------------
__device__ __forceinline__ void mma16816(float* d, const uint32_t* a, uint32_t b0, uint32_t b1) {
    asm volatile(
        "mma.sync.aligned.m16n8k16.row.col.f32.bf16.bf16.f32 "
        "{%0,%1,%2,%3}, {%4,%5,%6,%7}, {%8,%9}, {%0,%1,%2,%3};"
        : "+f"(d[0]), "+f"(d[1]), "+f"(d[2]), "+f"(d[3])
        : "r"(a[0]), "r"(a[1]), "r"(a[2]), "r"(a[3]), "r"(b0), "r"(b1));
}

__device__ __forceinline__ uint32_t split_pack(float x, float y, uint32_t& lo) {
    __nv_bfloat16 hx = __float2bfloat16(x), hy = __float2bfloat16(y);
    __nv_bfloat162 hp; hp.x = hx; hp.y = hy;
    __nv_bfloat162 lp;
    lp.x = __float2bfloat16(x - __bfloat162float(hx));
    lp.y = __float2bfloat16(y - __bfloat162float(hy));
    lo = *reinterpret_cast<uint32_t*>(&lp);
    return *reinterpret_cast<uint32_t*>(&hp);
}

// B-fragment builder for W[(64+k)][n] matrices (ldn = row stride)
__device__ __forceinline__ uint2 frag_make(const float* W, int ldn, int nt, int ks, int ln,
                                           uint2& lo) {
    int g = ln >> 2, tg = ln & 3;
    int n = 8 * nt + g, k0 = 16 * ks + 2 * tg;
    uint32_t l0, l1;
    uint32_t h0 = split_pack(W[(64 + k0)     * ldn + n], W[(64 + k0 + 1) * ldn + n], l0);
    uint32_t h1 = split_pack(W[(64 + k0 + 8) * ldn + n], W[(64 + k0 + 9) * ldn + n], l1);
    lo = make_uint2(l0, l1);
    return make_uint2(h0, h1);
}

// ---------------- Phase A (+fused sort): split-bf16 mma.sync GEMM ----------------
static constexpr int BIAS_OFF = 0;
static constexpr int AH_OFF   = 1536;
static constexpr int AL_OFF   = 19968;
static constexpr int BH_OFF   = 38400;
static constexpr int BL_OFF   = 93696;
static constexpr int PA_SMEM  = 148992;
#define SA 72

__device__ void sort_body(const int* __restrict__ seq_lens, char* dynsmem) {
    int* hist  = (int*)dynsmem;
    int* offs  = hist + T_;
    int tid = threadIdx.x;
    for (int i = tid; i < T_; i += 256) hist[i] = 0;
    __syncthreads();
    for (int i = tid; i < B_; i += 256) atomicAdd(&hist[T_ - 1 - seq_lens[i]], 1);
    __syncthreads();
    if (tid == 0) { int s = 0; for (int k = 0; k < T_; k++) { offs[k] = s; s += hist[k]; } }
    __syncthreads();
    for (int i = tid; i < T_; i += 256) hist[i] = 0;
    __syncthreads();
    for (int i = tid; i < B_; i += 256) {
        int key = T_ - 1 - seq_lens[i];
        g_order[offs[key] + atomicAdd(&hist[key], 1)] = i;
    }
}

__global__ void __launch_bounds__(256, 1) xproj_mma_kernel(
    const int* __restrict__ item_his, const int* __restrict__ seq_lens,
    const float* __restrict__ emb,
    const float* __restrict__ gk, const float* __restrict__ gb,
    const float* __restrict__ ck, const float* __restrict__ cb)
{
    extern __shared__ char dynsmem[];

    if (blockIdx.x == 2048) { sort_body(seq_lens, dynsmem); return; }

    float*         sBias = (float*)(dynsmem + BIAS_OFF);
    __nv_bfloat16* sAh   = (__nv_bfloat16*)(dynsmem + AH_OFF);
    __nv_bfloat16* sAl   = (__nv_bfloat16*)(dynsmem + AL_OFF);
    __nv_bfloat16* sBh   = (__nv_bfloat16*)(dynsmem + BH_OFF);
    __nv_bfloat16* sBl   = (__nv_bfloat16*)(dynsmem + BL_OFF);

    int b  = blockIdx.x >> 1;
    int t0 = (blockIdx.x & 1) << 7;
    if (t0 >= seq_lens[b]) return;

    int tid = threadIdx.x;

    for (int i = tid; i < GC; i += 256) sBias[i] = (i < 256) ? gb[i] : cb[i - 256];

    {
        int r = tid >> 1, half = tid & 1;
        int item = item_his[b * T_ + t0 + r];
        const float4* e4 = reinterpret_cast<const float4*>(emb + (size_t)item * D_ + half * 32);
        #pragma unroll
        for (int q = 0; q < 8; q++) {
            float4 v = e4[q];
            float f[4] = {v.x, v.y, v.z, v.w};
            int c0 = half * 32 + q * 4;
            #pragma unroll
            for (int i = 0; i < 2; i++) {
                uint32_t lo;
                uint32_t hi = split_pack(f[2*i], f[2*i+1], lo);
                *reinterpret_cast<uint32_t*>(&sAh[r * SA + c0 + 2*i]) = hi;
                *reinterpret_cast<uint32_t*>(&sAl[r * SA + c0 + 2*i]) = lo;
            }
        }
    }
    for (int idx = tid; idx < D_ * GC; idx += 256) {
        int k = idx / GC, n = idx - k * GC;
        float w = (n < 256) ? gk[k * 256 + n] : ck[k * 128 + (n - 256)];
        __nv_bfloat16 h = __float2bfloat16(w);
        sBh[n * SA + k] = h;
        sBl[n * SA + k] = __float2bfloat16(w - __bfloat162float(h));
    }
    __syncthreads();

    int wid = tid >> 5, lane = tid & 31;
    int gid = lane >> 2, tig = lane & 3;
    int m0 = wid * 16;

    uint32_t ah[4][4], al[4][4];
    #pragma unroll
    for (int ks = 0; ks < 4; ks++) {
        int c = ks * 16 + 2 * tig;
        ah[ks][0] = *reinterpret_cast<const uint32_t*>(&sAh[(m0+gid)   * SA + c]);
        ah[ks][1] = *reinterpret_cast<const uint32_t*>(&sAh[(m0+gid+8) * SA + c]);
        ah[ks][2] = *reinterpret_cast<const uint32_t*>(&sAh[(m0+gid)   * SA + c + 8]);
        ah[ks][3] = *reinterpret_cast<const uint32_t*>(&sAh[(m0+gid+8) * SA + c + 8]);
        al[ks][0] = *reinterpret_cast<const uint32_t*>(&sAl[(m0+gid)   * SA + c]);
        al[ks][1] = *reinterpret_cast<const uint32_t*>(&sAl[(m0+gid+8) * SA + c]);
        al[ks][2] = *reinterpret_cast<const uint32_t*>(&sAl[(m0+gid)   * SA + c + 8]);
        al[ks][3] = *reinterpret_cast<const uint32_t*>(&sAl[(m0+gid+8) * SA + c + 8]);
    }

    float* outbase = g_xproj + ((size_t)b * T_ + t0) * GC;

    for (int nt = 0; nt < 48; nt += 2) {
        float acc0[4] = {0.f, 0.f, 0.f, 0.f};
        float acc1[4] = {0.f, 0.f, 0.f, 0.f};
        #pragma unroll
        for (int ks = 0; ks < 4; ks++) {
            int c = ks * 16 + 2 * tig;
            int n0 = (nt * 8 + gid) * SA, n1 = ((nt + 1) * 8 + gid) * SA;
            uint32_t bh00 = *reinterpret_cast<const uint32_t*>(&sBh[n0 + c]);
            uint32_t bh01 = *reinterpret_cast<const uint32_t*>(&sBh[n0 + c + 8]);
            uint32_t bl00 = *reinterpret_cast<const uint32_t*>(&sBl[n0 + c]);
            uint32_t bl01 = *reinterpret_cast<const uint32_t*>(&sBl[n0 + c + 8]);
            uint32_t bh10 = *reinterpret_cast<const uint32_t*>(&sBh[n1 + c]);
            uint32_t bh11 = *reinterpret_cast<const uint32_t*>(&sBh[n1 + c + 8]);
            uint32_t bl10 = *reinterpret_cast<const uint32_t*>(&sBl[n1 + c]);
            uint32_t bl11 = *reinterpret_cast<const uint32_t*>(&sBl[n1 + c + 8]);
            mma16816(acc0, ah[ks], bh00, bh01);
            mma16816(acc1, ah[ks], bh10, bh11);
            mma16816(acc0, ah[ks], bl00, bl01);
            mma16816(acc1, ah[ks], bl10, bl11);
            mma16816(acc0, al[ks], bh00, bh01);
            mma16816(acc1, al[ks], bh10, bh11);
        }
        #pragma unroll
        for (int p = 0; p < 2; p++) {
            float* acc = p ? acc1 : acc0;
            int ncol = (nt + p) * 8 + 2 * tig;
            float2 bias = *reinterpret_cast<const float2*>(&sBias[ncol]);
            float2 o0 = {acc[0] + bias.x, acc[1] + bias.y};
            float2 o1 = {acc[2] + bias.x, acc[3] + bias.y};
            *reinterpret_cast<float2*>(outbase + (size_t)(m0 + gid)     * GC + ncol) = o0;
            *reinterpret_cast<float2*>(outbase + (size_t)(m0 + gid + 8) * GC + ncol) = o1;
        }
    }
}

// ---------------- Phase B: pipelined tensor-core GRU ----------------
// 64 CTAs x 16 rows (two 8-row groups X/Y, phase-shifted). 512 threads.
// Weight-hi fragments in registers; weight-lo fragments in smem.
static constexpr int OFF_BGL  = 0;        // u64[32nt][8ks][32ln] 65536 B
static constexpr int OFF_BCL  = 65536;    // u64[16][8][32]       32768 B
static constexpr int OFF_GRP  = 98304;    // 2 x 24832 B group state
static constexpr int GRP_SZ   = 24832;    // Ah,Al,Rh,Rl (4x4096) + H,U (2x4224)
static constexpr int OFF_META = OFF_GRP + 2 * GRP_SZ;   // 147968
static constexpr int G_SMEM   = OFF_META + 128;
#define HS 132

struct GPtr {
    uint32_t *Ah, *Al, *Rh, *Rl;
    float *H, *U;
    int xoff, len;
};

__device__ __forceinline__ void gate_phase(
    const GPtr& G, int t,
    const uint2* BgH0, const uint2* BgH1, const uint2* sBgL,
    int lane, int nt0, int nt1, int gid, int cA0, int cA1, bool isR, int rhOff)
{
    bool act = t < G.len;
    float2 xg0 = make_float2(0.f, 0.f), xg1 = make_float2(0.f, 0.f);
    if (act) {
        int base = G.xoff + t * GC;
        xg0 = *reinterpret_cast<const float2*>(&g_xproj[base + cA0]);
        xg1 = *reinterpret_cast<const float2*>(&g_xproj[base + cA1]);
    }
    float a0h[4] = {0.f,0.f,0.f,0.f}, a0l[4] = {0.f,0.f,0.f,0.f};
    float a1h[4] = {0.f,0.f,0.f,0.f}, a1l[4] = {0.f,0.f,0.f,0.f};
    #pragma unroll
    for (int ks = 0; ks < 8; ks++) {
        uint4 ah4 = *reinterpret_cast<const uint4*>(&G.Ah[(ks * 32 + lane) * 4]);
        uint4 al4 = *reinterpret_cast<const uint4*>(&G.Al[(ks * 32 + lane) * 4]);
        uint2 bl0 = sBgL[(nt0 * 8 + ks) * 32 + lane];
        uint2 bl1 = sBgL[(nt1 * 8 + ks) * 32 + lane];
        const uint32_t* ah = reinterpret_cast<const uint32_t*>(&ah4);
        const uint32_t* al = reinterpret_cast<const uint32_t*>(&al4);
        mma16816(a0h, ah, BgH0[ks].x, BgH0[ks].y);
        mma16816(a1h, ah, BgH1[ks].x, BgH1[ks].y);
        mma16816(a0l, al, BgH0[ks].x, BgH0[ks].y);
        mma16816(a1l, al, BgH1[ks].x, BgH1[ks].y);
        mma16816(a0l, ah, bl0.x, bl0.y);
        mma16816(a1l, ah, bl1.x, bl1.y);
    }
    float s0 = sigmoidf_(a0h[0] + a0l[0] + xg0.x);
    float s1 = sigmoidf_(a0h[1] + a0l[1] + xg0.y);
    float s2 = sigmoidf_(a1h[0] + a1l[0] + xg1.x);
    float s3 = sigmoidf_(a1h[1] + a1l[1] + xg1.y);
    if (isR) {
        float2 h01 = *reinterpret_cast<const float2*>(&G.H[gid * HS + cA0]);
        float2 h23 = *reinterpret_cast<const float2*>(&G.H[gid * HS + cA1]);
        uint32_t lo;
        uint32_t hi = split_pack(s0 * h01.x, s1 * h01.y, lo);
        G.Rh[rhOff]     = hi; G.Rl[rhOff]     = lo;
        hi = split_pack(s2 * h23.x, s3 * h23.y, lo);
        G.Rh[rhOff + 2] = hi; G.Rl[rhOff + 2] = lo;
    } else {
        *reinterpret_cast<float2*>(&G.U[gid * HS + cA0 - 128]) = make_float2(s0, s1);
        *reinterpret_cast<float2*>(&G.U[gid * HS + cA1 - 128]) = make_float2(s2, s3);
    }
}

__device__ __forceinline__ void cand_phase(
    const GPtr& G, int t, const uint2* BcH, const uint2* sBcL,
    int lane, int wid, int gid, int j0, int ahOff)
{
    bool act = t < G.len;
    float2 xc = make_float2(0.f, 0.f);
    if (act) xc = *reinterpret_cast<const float2*>(&g_xproj[G.xoff + t * GC + 256 + j0]);
    float2 uu   = *reinterpret_cast<const float2*>(&G.U[gid * HS + j0]);
    float2 hold = *reinterpret_cast<const float2*>(&G.H[gid * HS + j0]);
    float ch[4] = {0.f,0.f,0.f,0.f}, cl[4] = {0.f,0.f,0.f,0.f};
    #pragma unroll
    for (int ks = 0; ks < 8; ks++) {
        uint4 ah4 = *reinterpret_cast<const uint4*>(&G.Rh[(ks * 32 + lane) * 4]);
        uint4 al4 = *reinterpret_cast<const uint4*>(&G.Rl[(ks * 32 + lane) * 4]);
        uint2 bl = sBcL[(wid * 8 + ks) * 32 + lane];
        const uint32_t* ah = reinterpret_cast<const uint32_t*>(&ah4);
        const uint32_t* al = reinterpret_cast<const uint32_t*>(&al4);
        mma16816(ch, ah, BcH[ks].x, BcH[ks].y);
        mma16816(cl, al, BcH[ks].x, BcH[ks].y);
        mma16816(cl, ah, bl.x, bl.y);
    }
    if (act) {
        float cc0 = tanhf_(ch[0] + cl[0] + xc.x);
        float cc1 = tanhf_(ch[1] + cl[1] + xc.y);
        float hn0 = uu.x * hold.x + (1.0f - uu.x) * cc0;
        float hn1 = uu.y * hold.y + (1.0f - uu.y) * cc1;
        *reinterpret_cast<float2*>(&G.H[gid * HS + j0]) = make_float2(hn0, hn1);
        uint32_t lo;
        uint32_t hi = split_pack(hn0, hn1, lo);
        G.Ah[ahOff] = hi;
        G.Al[ahOff] = lo;
    }
}

__global__ void __launch_bounds__(512, 1) gru_mma2_kernel(
    const int* __restrict__ seq_lens,
    const float* __restrict__ gk, const float* __restrict__ ck,
    float* __restrict__ out)
{
    extern __shared__ char dynsmem[];
    uint2* sBgL = (uint2*)(dynsmem + OFF_BGL);
    uint2* sBcL = (uint2*)(dynsmem + OFF_BCL);
    int* srow = (int*)(dynsmem + OFF_META);
    int* slen = srow + 16;

    int tid = threadIdx.x;
    int wid = tid >> 5, lane = tid & 31;
    int gid = lane >> 2, tig = lane & 3;
    int nt0 = 2 * wid, nt1 = nt0 + 1;

    GPtr X, Y;
    {
        char* b0 = dynsmem + OFF_GRP;
        char* b1 = b0 + GRP_SZ;
        X.Ah = (uint32_t*)(b0);         X.Al = (uint32_t*)(b0 + 4096);
        X.Rh = (uint32_t*)(b0 + 8192);  X.Rl = (uint32_t*)(b0 + 12288);
        X.H  = (float*)(b0 + 16384);    X.U  = (float*)(b0 + 20608);
        Y.Ah = (uint32_t*)(b1);         Y.Al = (uint32_t*)(b1 + 4096);
        Y.Rh = (uint32_t*)(b1 + 8192);  Y.Rl = (uint32_t*)(b1 + 12288);
        Y.H  = (float*)(b1 + 16384);    Y.U  = (float*)(b1 + 20608);
    }

    // init: weight-lo fragments in smem
    for (int idx = tid; idx < 32 * 8 * 32; idx += 512) {
        uint2 lo;
        frag_make(gk, 256, idx >> 8, (idx >> 5) & 7, idx & 31, lo);
        sBgL[idx] = lo;
    }
    for (int idx = tid; idx < 16 * 8 * 32; idx += 512) {
        uint2 lo;
        frag_make(ck, 128, idx >> 8, (idx >> 5) & 7, idx & 31, lo);
        sBcL[idx] = lo;
    }
    // weight-hi fragments in registers
    uint2 BgH0[8], BgH1[8], BcH[8];
    #pragma unroll
    for (int ks = 0; ks < 8; ks++) {
        uint2 dump;
        BgH0[ks] = frag_make(gk, 256, nt0, ks, lane, dump);
        BgH1[ks] = frag_make(gk, 256, nt1, ks, lane, dump);
        BcH[ks]  = frag_make(ck, 128, wid, ks, lane, dump);
    }
    // zero state
    for (int i = tid; i < 1024; i += 512) {
        X.Ah[i] = 0u; X.Al[i] = 0u; X.Rh[i] = 0u; X.Rl[i] = 0u;
        Y.Ah[i] = 0u; Y.Al[i] = 0u; Y.Rh[i] = 0u; Y.Rl[i] = 0u;
    }
    for (int i = tid; i < 8 * HS; i += 512) {
        X.H[i] = 0.0f; X.U[i] = 0.0f; Y.H[i] = 0.0f; Y.U[i] = 0.0f;
    }
    if (tid < 16) {
        int row = g_order[blockIdx.x * 16 + tid];
        srow[tid] = row;
        slen[tid] = seq_lens[row];
    }
    __syncthreads();

    X.len = slen[gid];     X.xoff = srow[gid]     * (T_ * GC);
    Y.len = slen[8 + gid]; Y.xoff = srow[8 + gid] * (T_ * GC);

    int cA0 = 16 * wid + 2 * tig;
    int cA1 = cA0 + 8;
    int j0  = 8 * wid + 2 * tig;
    bool isR = (wid < 8);
    int rhOff = ((wid & 7) * 32 + lane) * 4;
    int ahOff = ((j0 >> 4) * 32 + lane) * 4 + ((wid & 1) ? 2 : 0);

    int maxlen = slen[0];

    for (int t = 0; t < maxlen; t++) {
        // interval A: gate X(t)  ||  cand Y(t-1)
        gate_phase(X, t, BgH0, BgH1, sBgL, lane, nt0, nt1, gid, cA0, cA1, isR, rhOff);
        if (t > 0) cand_phase(Y, t - 1, BcH, sBcL, lane, wid, gid, j0, ahOff);
        __syncthreads();
        // interval B: gate Y(t)  ||  cand X(t)
        gate_phase(Y, t, BgH0, BgH1, sBgL, lane, nt0, nt1, gid, cA0, cA1, isR, rhOff);
        cand_phase(X, t, BcH, sBcL, lane, wid, gid, j0, ahOff);
        __syncthreads();
    }
    if (maxlen > 0)
        cand_phase(Y, maxlen - 1, BcH, sBcL, lane, wid, gid, j0, ahOff);

    // output (thread owns h[gid][j0..j0+1] of both groups)
    *reinterpret_cast<float2*>(&out[(size_t)srow[gid]     * H_ + j0]) =
        *reinterpret_cast<const float2*>(&X.H[gid * HS + j0]);
    *reinterpret_cast<float2*>(&out[(size_t)srow[8 + gid] * H_ + j0]) =
        *reinterpret_cast<const float2*>(&Y.H[gid * HS + j0]);
}

// ---------------- launch ----------------
extern "C" void kernel_launch(void* const* d_in, const int* in_sizes, int n_in,
                              void* d_out, int out_size) {
    const int*   item_his = (const int*)  d_in[0];
    const int*   seq_lens = (const int*)  d_in[1];
    const float* emb      = (const float*)d_in[2];
    const float* gk       = (const float*)d_in[3];
    const float* gb       = (const float*)d_in[4];
    const float* ck       = (const float*)d_in[5];
    const float* cb       = (const float*)d_in[6];
    float*       out      = (float*)d_out;

    cudaFuncSetAttribute(xproj_mma_kernel, cudaFuncAttributeMaxDynamicSharedMemorySize, PA_SMEM);
    cudaFuncSetAttribute(gru_mma2_kernel,  cudaFuncAttributeMaxDynamicSharedMemorySize, G_SMEM);

    xproj_mma_kernel<<<2049, 256, PA_SMEM>>>(item_his, seq_lens, emb, gk, gb, ck, cb);
    gru_mma2_kernel<<<B_ / 16, 512, G_SMEM>>>(seq_lens, gk, ck, out);
}

// round 11
// speedup vs baseline: 1.7554x; 1.7554x over previous
#include <cuda_runtime.h>
#include <cuda_bf16.h>
#include <cstdint>

#define B_    1024
#define T_    256
#define D_    64
#define H_    128
#define GC    384

__device__ float g_xproj[(size_t)B_ * T_ * GC];
__device__ int   g_order[B_];

__device__ __forceinline__ float sigmoidf_(float x) {
    return __fdividef(1.0f, 1.0f + __expf(-x));
}
__device__ __forceinline__ float tanhf_(float x) {
    return 1.0f - __fdividef(2.0f, __expf(2.0f * x) + 1.0f);
}

// ---------------- warp-level bf16 MMA ----------------
__device__ __forceinline__ void mma16816(float* d, const uint32_t* a, uint32_t b0, uint32_t b1) {
    asm volatile(
        "mma.sync.aligned.m16n8k16.row.col.f32.bf16.bf16.f32 "
        "{%0,%1,%2,%3}, {%4,%5,%6,%7}, {%8,%9}, {%0,%1,%2,%3};"
        : "+f"(d[0]), "+f"(d[1]), "+f"(d[2]), "+f"(d[3])
        : "r"(a[0]), "r"(a[1]), "r"(a[2]), "r"(a[3]), "r"(b0), "r"(b1));
}

__device__ __forceinline__ uint32_t split_pack(float x, float y, uint32_t& lo) {
    __nv_bfloat16 hx = __float2bfloat16(x), hy = __float2bfloat16(y);
    __nv_bfloat162 hp; hp.x = hx; hp.y = hy;
    __nv_bfloat162 lp;
    lp.x = __float2bfloat16(x - __bfloat162float(hx));
    lp.y = __float2bfloat16(y - __bfloat162float(hy));
    lo = *reinterpret_cast<uint32_t*>(&lp);
    return *reinterpret_cast<uint32_t*>(&hp);
}

// B-fragment builder for W[(64+k)][n] matrices (ldn = row stride)
__device__ __forceinline__ uint2 frag_make(const float* W, int ldn, int nt, int ks, int ln,
                                           uint2& lo) {
    int g = ln >> 2, tg = ln & 3;
    int n = 8 * nt + g, k0 = 16 * ks + 2 * tg;
    uint32_t l0, l1;
    uint32_t h0 = split_pack(W[(64 + k0)     * ldn + n], W[(64 + k0 + 1) * ldn + n], l0);
    uint32_t h1 = split_pack(W[(64 + k0 + 8) * ldn + n], W[(64 + k0 + 9) * ldn + n], l1);
    lo = make_uint2(l0, l1);
    return make_uint2(h0, h1);
}

// ---------------- Phase A (+fused sort): split-bf16 mma.sync GEMM ----------------
static constexpr int BIAS_OFF = 0;
static constexpr int AH_OFF   = 1536;
static constexpr int AL_OFF   = 19968;
static constexpr int BH_OFF   = 38400;
static constexpr int BL_OFF   = 93696;
static constexpr int PA_SMEM  = 148992;
#define SA 72

__device__ void sort_body(const int* __restrict__ seq_lens, char* dynsmem) {
    int* hist  = (int*)dynsmem;
    int* offs  = hist + T_;
    int tid = threadIdx.x;
    for (int i = tid; i < T_; i += 256) hist[i] = 0;
    __syncthreads();
    for (int i = tid; i < B_; i += 256) atomicAdd(&hist[T_ - 1 - seq_lens[i]], 1);
    __syncthreads();
    if (tid == 0) { int s = 0; for (int k = 0; k < T_; k++) { offs[k] = s; s += hist[k]; } }
    __syncthreads();
    for (int i = tid; i < T_; i += 256) hist[i] = 0;
    __syncthreads();
    for (int i = tid; i < B_; i += 256) {
        int key = T_ - 1 - seq_lens[i];
        g_order[offs[key] + atomicAdd(&hist[key], 1)] = i;
    }
}

__global__ void __launch_bounds__(256, 1) xproj_mma_kernel(
    const int* __restrict__ item_his, const int* __restrict__ seq_lens,
    const float* __restrict__ emb,
    const float* __restrict__ gk, const float* __restrict__ gb,
    const float* __restrict__ ck, const float* __restrict__ cb)
{
    extern __shared__ char dynsmem[];

    if (blockIdx.x == 2048) { sort_body(seq_lens, dynsmem); return; }

    float*         sBias = (float*)(dynsmem + BIAS_OFF);
    __nv_bfloat16* sAh   = (__nv_bfloat16*)(dynsmem + AH_OFF);
    __nv_bfloat16* sAl   = (__nv_bfloat16*)(dynsmem + AL_OFF);
    __nv_bfloat16* sBh   = (__nv_bfloat16*)(dynsmem + BH_OFF);
    __nv_bfloat16* sBl   = (__nv_bfloat16*)(dynsmem + BL_OFF);

    int b  = blockIdx.x >> 1;
    int t0 = (blockIdx.x & 1) << 7;
    if (t0 >= seq_lens[b]) return;

    int tid = threadIdx.x;

    for (int i = tid; i < GC; i += 256) sBias[i] = (i < 256) ? gb[i] : cb[i - 256];

    {
        int r = tid >> 1, half = tid & 1;
        int item = item_his[b * T_ + t0 + r];
        const float4* e4 = reinterpret_cast<const float4*>(emb + (size_t)item * D_ + half * 32);
        #pragma unroll
        for (int q = 0; q < 8; q++) {
            float4 v = e4[q];
            float f[4] = {v.x, v.y, v.z, v.w};
            int c0 = half * 32 + q * 4;
            #pragma unroll
            for (int i = 0; i < 2; i++) {
                uint32_t lo;
                uint32_t hi = split_pack(f[2*i], f[2*i+1], lo);
                *reinterpret_cast<uint32_t*>(&sAh[r * SA + c0 + 2*i]) = hi;
                *reinterpret_cast<uint32_t*>(&sAl[r * SA + c0 + 2*i]) = lo;
            }
        }
    }
    for (int idx = tid; idx < D_ * GC; idx += 256) {
        int k = idx / GC, n = idx - k * GC;
        float w = (n < 256) ? gk[k * 256 + n] : ck[k * 128 + (n - 256)];
        __nv_bfloat16 h = __float2bfloat16(w);
        sBh[n * SA + k] = h;
        sBl[n * SA + k] = __float2bfloat16(w - __bfloat162float(h));
    }
    __syncthreads();

    int wid = tid >> 5, lane = tid & 31;
    int gid = lane >> 2, tig = lane & 3;
    int m0 = wid * 16;

    uint32_t ah[4][4], al[4][4];
    #pragma unroll
    for (int ks = 0; ks < 4; ks++) {
        int c = ks * 16 + 2 * tig;
        ah[ks][0] = *reinterpret_cast<const uint32_t*>(&sAh[(m0+gid)   * SA + c]);
        ah[ks][1] = *reinterpret_cast<const uint32_t*>(&sAh[(m0+gid+8) * SA + c]);
        ah[ks][2] = *reinterpret_cast<const uint32_t*>(&sAh[(m0+gid)   * SA + c + 8]);
        ah[ks][3] = *reinterpret_cast<const uint32_t*>(&sAh[(m0+gid+8) * SA + c + 8]);
        al[ks][0] = *reinterpret_cast<const uint32_t*>(&sAl[(m0+gid)   * SA + c]);
        al[ks][1] = *reinterpret_cast<const uint32_t*>(&sAl[(m0+gid+8) * SA + c]);
        al[ks][2] = *reinterpret_cast<const uint32_t*>(&sAl[(m0+gid)   * SA + c + 8]);
        al[ks][3] = *reinterpret_cast<const uint32_t*>(&sAl[(m0+gid+8) * SA + c + 8]);
    }

    float* outbase = g_xproj + ((size_t)b * T_ + t0) * GC;

    for (int nt = 0; nt < 48; nt += 2) {
        float acc0[4] = {0.f, 0.f, 0.f, 0.f};
        float acc1[4] = {0.f, 0.f, 0.f, 0.f};
        #pragma unroll
        for (int ks = 0; ks < 4; ks++) {
            int c = ks * 16 + 2 * tig;
            int n0 = (nt * 8 + gid) * SA, n1 = ((nt + 1) * 8 + gid) * SA;
            uint32_t bh00 = *reinterpret_cast<const uint32_t*>(&sBh[n0 + c]);
            uint32_t bh01 = *reinterpret_cast<const uint32_t*>(&sBh[n0 + c + 8]);
            uint32_t bl00 = *reinterpret_cast<const uint32_t*>(&sBl[n0 + c]);
            uint32_t bl01 = *reinterpret_cast<const uint32_t*>(&sBl[n0 + c + 8]);
            uint32_t bh10 = *reinterpret_cast<const uint32_t*>(&sBh[n1 + c]);
            uint32_t bh11 = *reinterpret_cast<const uint32_t*>(&sBh[n1 + c + 8]);
            uint32_t bl10 = *reinterpret_cast<const uint32_t*>(&sBl[n1 + c]);
            uint32_t bl11 = *reinterpret_cast<const uint32_t*>(&sBl[n1 + c + 8]);
            mma16816(acc0, ah[ks], bh00, bh01);
            mma16816(acc1, ah[ks], bh10, bh11);
            mma16816(acc0, ah[ks], bl00, bl01);
            mma16816(acc1, ah[ks], bl10, bl11);
            mma16816(acc0, al[ks], bh00, bh01);
            mma16816(acc1, al[ks], bh10, bh11);
        }
        #pragma unroll
        for (int p = 0; p < 2; p++) {
            float* acc = p ? acc1 : acc0;
            int ncol = (nt + p) * 8 + 2 * tig;
            float2 bias = *reinterpret_cast<const float2*>(&sBias[ncol]);
            float2 o0 = {acc[0] + bias.x, acc[1] + bias.y};
            float2 o1 = {acc[2] + bias.x, acc[3] + bias.y};
            *reinterpret_cast<float2*>(outbase + (size_t)(m0 + gid)     * GC + ncol) = o0;
            *reinterpret_cast<float2*>(outbase + (size_t)(m0 + gid + 8) * GC + ncol) = o1;
        }
    }
}

// ---------------- Phase B: tensor-core GRU, short chains + cross-step prefetch -------
// 128 CTAs x 8 rows, 512 threads. Weight-hi frags in regs, weight-lo in smem.
static constexpr int OFF_BGL  = 0;        // uint2[32nt][8ks][32ln] 65536 B
static constexpr int OFF_BCL  = 65536;    // uint2[16][8][32]       32768 B
static constexpr int OFF_AH   = 98304;    // u32[8ks][32ln][4]      4096 B
static constexpr int OFF_AL   = 102400;
static constexpr int OFF_RH   = 106496;
static constexpr int OFF_RL   = 110592;
static constexpr int OFF_H    = 114688;   // f32[8][132]            4224 B
static constexpr int OFF_U    = 118912;
static constexpr int OFF_META = 123136;
static constexpr int G_SMEM   = 123264;
#define HS 132

__global__ void __launch_bounds__(512, 1) gru_mma_kernel(
    const int* __restrict__ seq_lens,
    const float* __restrict__ gk, const float* __restrict__ ck,
    float* __restrict__ out)
{
    extern __shared__ char dynsmem[];
    uint2* sBgL = (uint2*)(dynsmem + OFF_BGL);
    uint2* sBcL = (uint2*)(dynsmem + OFF_BCL);
    uint32_t* sAh = (uint32_t*)(dynsmem + OFF_AH);
    uint32_t* sAl = (uint32_t*)(dynsmem + OFF_AL);
    uint32_t* sRh = (uint32_t*)(dynsmem + OFF_RH);
    uint32_t* sRl = (uint32_t*)(dynsmem + OFF_RL);
    float* sH = (float*)(dynsmem + OFF_H);
    float* sU = (float*)(dynsmem + OFF_U);
    int* srow = (int*)(dynsmem + OFF_META);
    int* slen = srow + 8;

    int tid = threadIdx.x;
    int wid = tid >> 5, lane = tid & 31;
    int gid = lane >> 2, tig = lane & 3;
    int nt0 = 2 * wid, nt1 = nt0 + 1;

    // weight-lo fragments -> smem
    for (int idx = tid; idx < 32 * 8 * 32; idx += 512) {
        uint2 lo;
        frag_make(gk, 256, idx >> 8, (idx >> 5) & 7, idx & 31, lo);
        sBgL[idx] = lo;
    }
    for (int idx = tid; idx < 16 * 8 * 32; idx += 512) {
        uint2 lo;
        frag_make(ck, 128, idx >> 8, (idx >> 5) & 7, idx & 31, lo);
        sBcL[idx] = lo;
    }
    // weight-hi fragments -> registers
    uint2 BgH0[8], BgH1[8], BcH[8];
    #pragma unroll
    for (int ks = 0; ks < 8; ks++) {
        uint2 dump;
        BgH0[ks] = frag_make(gk, 256, nt0, ks, lane, dump);
        BgH1[ks] = frag_make(gk, 256, nt1, ks, lane, dump);
        BcH[ks]  = frag_make(ck, 128, wid, ks, lane, dump);
    }
    // zero state
    for (int i = tid; i < 1024; i += 512) {
        sAh[i] = 0u; sAl[i] = 0u; sRh[i] = 0u; sRl[i] = 0u;
    }
    for (int i = tid; i < 8 * HS; i += 512) { sH[i] = 0.0f; sU[i] = 0.0f; }
    if (tid < 8) {
        int row = g_order[blockIdx.x * 8 + tid];
        srow[tid] = row;
        slen[tid] = seq_lens[row];
    }
    __syncthreads();

    int maxlen = slen[0];
    int mylen  = slen[gid];
    int myxoff = srow[gid] * (T_ * GC);
    int cA0 = 16 * wid + 2 * tig;
    int cA1 = cA0 + 8;
    int j0  = 8 * wid + 2 * tig;
    bool isR = (wid < 8);
    int rhOff = ((wid & 7) * 32 + lane) * 4;
    int ahOff = ((j0 >> 4) * 32 + lane) * 4 + ((wid & 1) ? 2 : 0);

    // preload x-projections for t = 0
    float2 xg0 = make_float2(0.f, 0.f), xg1 = make_float2(0.f, 0.f), xc = make_float2(0.f, 0.f);
    if (0 < mylen) {
        xg0 = *reinterpret_cast<const float2*>(&g_xproj[myxoff + cA0]);
        xg1 = *reinterpret_cast<const float2*>(&g_xproj[myxoff + cA1]);
        xc  = *reinterpret_cast<const float2*>(&g_xproj[myxoff + 256 + j0]);
    }

    for (int t = 0; t < maxlen; t++) {
        // prefetch t+1 (consumed next iteration -> full-step DRAM cover)
        float2 xg0n = make_float2(0.f, 0.f), xg1n = make_float2(0.f, 0.f);
        float2 xcn  = make_float2(0.f, 0.f);
        if (t + 1 < mylen) {
            int bn = myxoff + (t + 1) * GC;
            xg0n = *reinterpret_cast<const float2*>(&g_xproj[bn + cA0]);
            xg1n = *reinterpret_cast<const float2*>(&g_xproj[bn + cA1]);
            xcn  = *reinterpret_cast<const float2*>(&g_xproj[bn + 256 + j0]);
        }
        bool act = (t < mylen);

        // ---- gate MMA: 6 independent 8-deep chains ----
        float a0h[4] = {0.f,0.f,0.f,0.f}, a0m[4] = {0.f,0.f,0.f,0.f}, a0l[4] = {0.f,0.f,0.f,0.f};
        float a1h[4] = {0.f,0.f,0.f,0.f}, a1m[4] = {0.f,0.f,0.f,0.f}, a1l[4] = {0.f,0.f,0.f,0.f};
        #pragma unroll
        for (int ks = 0; ks < 8; ks++) {
            uint4 ah4 = *reinterpret_cast<const uint4*>(&sAh[(ks * 32 + lane) * 4]);
            uint4 al4 = *reinterpret_cast<const uint4*>(&sAl[(ks * 32 + lane) * 4]);
            uint2 bl0 = sBgL[(nt0 * 8 + ks) * 32 + lane];
            uint2 bl1 = sBgL[(nt1 * 8 + ks) * 32 + lane];
            const uint32_t* ah = reinterpret_cast<const uint32_t*>(&ah4);
            const uint32_t* al = reinterpret_cast<const uint32_t*>(&al4);
            mma16816(a0h, ah, BgH0[ks].x, BgH0[ks].y);
            mma16816(a1h, ah, BgH1[ks].x, BgH1[ks].y);
            mma16816(a0m, al, BgH0[ks].x, BgH0[ks].y);
            mma16816(a1m, al, BgH1[ks].x, BgH1[ks].y);
            mma16816(a0l, ah, bl0.x, bl0.y);
            mma16816(a1l, ah, bl1.x, bl1.y);
        }
        float s0 = sigmoidf_(a0h[0] + a0m[0] + a0l[0] + xg0.x);
        float s1 = sigmoidf_(a0h[1] + a0m[1] + a0l[1] + xg0.y);
        float s2 = sigmoidf_(a1h[0] + a1m[0] + a1l[0] + xg1.x);
        float s3 = sigmoidf_(a1h[1] + a1m[1] + a1l[1] + xg1.y);
        if (isR) {
            float2 h01 = *reinterpret_cast<const float2*>(&sH[gid * HS + cA0]);
            float2 h23 = *reinterpret_cast<const float2*>(&sH[gid * HS + cA1]);
            uint32_t lo;
            uint32_t hi = split_pack(s0 * h01.x, s1 * h01.y, lo);
            sRh[rhOff]     = hi; sRl[rhOff]     = lo;
            hi = split_pack(s2 * h23.x, s3 * h23.y, lo);
            sRh[rhOff + 2] = hi; sRl[rhOff + 2] = lo;
        } else {
            *reinterpret_cast<float2*>(&sU[gid * HS + cA0 - 128]) = make_float2(s0, s1);
            *reinterpret_cast<float2*>(&sU[gid * HS + cA1 - 128]) = make_float2(s2, s3);
        }
        __syncthreads();

        float2 uu   = *reinterpret_cast<const float2*>(&sU[gid * HS + j0]);
        float2 hold = *reinterpret_cast<const float2*>(&sH[gid * HS + j0]);

        // ---- cand MMA: 3 independent 8-deep chains ----
        float ch[4] = {0.f,0.f,0.f,0.f}, cm[4] = {0.f,0.f,0.f,0.f}, cl[4] = {0.f,0.f,0.f,0.f};
        #pragma unroll
        for (int ks = 0; ks < 8; ks++) {
            uint4 ah4 = *reinterpret_cast<const uint4*>(&sRh[(ks * 32 + lane) * 4]);
            uint4 al4 = *reinterpret_cast<const uint4*>(&sRl[(ks * 32 + lane) * 4]);
            uint2 bl = sBcL[(wid * 8 + ks) * 32 + lane];
            const uint32_t* ah = reinterpret_cast<const uint32_t*>(&ah4);
            const uint32_t* al = reinterpret_cast<const uint32_t*>(&al4);
            mma16816(ch, ah, BcH[ks].x, BcH[ks].y);
            mma16816(cm, al, BcH[ks].x, BcH[ks].y);
            mma16816(cl, ah, bl.x, bl.y);
        }

        // ---- update (this thread owns h[gid][j0..j0+1]) ----
        if (act) {
            float cc0 = tanhf_(ch[0] + cm[0] + cl[0] + xc.x);
            float cc1 = tanhf_(ch[1] + cm[1] + cl[1] + xc.y);
            float hn0 = uu.x * hold.x + (1.0f - uu.x) * cc0;
            float hn1 = uu.y * hold.y + (1.0f - uu.y) * cc1;
            *reinterpret_cast<float2*>(&sH[gid * HS + j0]) = make_float2(hn0, hn1);
            uint32_t lo;
            uint32_t hi = split_pack(hn0, hn1, lo);
            sAh[ahOff] = hi;
            sAl[ahOff] = lo;
        }
        __syncthreads();

        xg0 = xg0n; xg1 = xg1n; xc = xcn;
    }

    // output: thread owns h[gid][j0..j0+1]
    float2 hv = *reinterpret_cast<const float2*>(&sH[gid * HS + j0]);
    *reinterpret_cast<float2*>(&out[(size_t)srow[gid] * H_ + j0]) = hv;
}

// ---------------- launch ----------------
extern "C" void kernel_launch(void* const* d_in, const int* in_sizes, int n_in,
                              void* d_out, int out_size) {
    const int*   item_his = (const int*)  d_in[0];
    const int*   seq_lens = (const int*)  d_in[1];
    const float* emb      = (const float*)d_in[2];
    const float* gk       = (const float*)d_in[3];
    const float* gb       = (const float*)d_in[4];
    const float* ck       = (const float*)d_in[5];
    const float* cb       = (const float*)d_in[6];
    float*       out      = (float*)d_out;

    cudaFuncSetAttribute(xproj_mma_kernel, cudaFuncAttributeMaxDynamicSharedMemorySize, PA_SMEM);
    cudaFuncSetAttribute(gru_mma_kernel,   cudaFuncAttributeMaxDynamicSharedMemorySize, G_SMEM);

    xproj_mma_kernel<<<2049, 256, PA_SMEM>>>(item_his, seq_lens, emb, gk, gb, ck, cb);
    gru_mma_kernel<<<B_ / 8, 512, G_SMEM>>>(seq_lens, gk, ck, out);
}

// round 12
// speedup vs baseline: 2.1041x; 1.1986x over previous
#include <cuda_runtime.h>
#include <cuda_bf16.h>
#include <cstdint>

#define B_    1024
#define T_    256
#define D_    64
#define H_    128
#define GC    384

__device__ float g_xproj[(size_t)B_ * T_ * GC];
__device__ int   g_order[B_];

__device__ __forceinline__ float sigmoidf_(float x) {
    return __fdividef(1.0f, 1.0f + __expf(-x));
}
__device__ __forceinline__ float tanhf_(float x) {
    return 1.0f - __fdividef(2.0f, __expf(2.0f * x) + 1.0f);
}

// ---------------- warp-level bf16 MMA ----------------
__device__ __forceinline__ void mma16816(float* d, const uint32_t* a, uint32_t b0, uint32_t b1) {
    asm volatile(
        "mma.sync.aligned.m16n8k16.row.col.f32.bf16.bf16.f32 "
        "{%0,%1,%2,%3}, {%4,%5,%6,%7}, {%8,%9}, {%0,%1,%2,%3};"
        : "+f"(d[0]), "+f"(d[1]), "+f"(d[2]), "+f"(d[3])
        : "r"(a[0]), "r"(a[1]), "r"(a[2]), "r"(a[3]), "r"(b0), "r"(b1));
}

__device__ __forceinline__ uint32_t split_pack(float x, float y, uint32_t& lo) {
    __nv_bfloat16 hx = __float2bfloat16(x), hy = __float2bfloat16(y);
    __nv_bfloat162 hp; hp.x = hx; hp.y = hy;
    __nv_bfloat162 lp;
    lp.x = __float2bfloat16(x - __bfloat162float(hx));
    lp.y = __float2bfloat16(y - __bfloat162float(hy));
    lo = *reinterpret_cast<uint32_t*>(&lp);
    return *reinterpret_cast<uint32_t*>(&hp);
}

// B-fragment builder for W[(64+k)][n] matrices (ldn = row stride)
__device__ __forceinline__ uint2 frag_make(const float* W, int ldn, int nt, int ks, int ln,
                                           uint2& lo) {
    int g = ln >> 2, tg = ln & 3;
    int n = 8 * nt + g, k0 = 16 * ks + 2 * tg;
    uint32_t l0, l1;
    uint32_t h0 = split_pack(W[(64 + k0)     * ldn + n], W[(64 + k0 + 1) * ldn + n], l0);
    uint32_t h1 = split_pack(W[(64 + k0 + 8) * ldn + n], W[(64 + k0 + 9) * ldn + n], l1);
    lo = make_uint2(l0, l1);
    return make_uint2(h0, h1);
}

// ---------------- Phase A (+fused sort): split-bf16 mma.sync GEMM ----------------
static constexpr int BIAS_OFF = 0;
static constexpr int AH_OFF   = 1536;
static constexpr int AL_OFF   = 19968;
static constexpr int BH_OFF   = 38400;
static constexpr int BL_OFF   = 93696;
static constexpr int PA_SMEM  = 148992;
#define SA 72

__device__ void sort_body(const int* __restrict__ seq_lens, char* dynsmem) {
    int* hist  = (int*)dynsmem;
    int* offs  = hist + T_;
    int tid = threadIdx.x;
    for (int i = tid; i < T_; i += 256) hist[i] = 0;
    __syncthreads();
    for (int i = tid; i < B_; i += 256) atomicAdd(&hist[T_ - 1 - seq_lens[i]], 1);
    __syncthreads();
    if (tid == 0) { int s = 0; for (int k = 0; k < T_; k++) { offs[k] = s; s += hist[k]; } }
    __syncthreads();
    for (int i = tid; i < T_; i += 256) hist[i] = 0;
    __syncthreads();
    for (int i = tid; i < B_; i += 256) {
        int key = T_ - 1 - seq_lens[i];
        g_order[offs[key] + atomicAdd(&hist[key], 1)] = i;
    }
}

__global__ void __launch_bounds__(256, 1) xproj_mma_kernel(
    const int* __restrict__ item_his, const int* __restrict__ seq_lens,
    const float* __restrict__ emb,
    const float* __restrict__ gk, const float* __restrict__ gb,
    const float* __restrict__ ck, const float* __restrict__ cb)
{
    extern __shared__ char dynsmem[];

    if (blockIdx.x == 2048) { sort_body(seq_lens, dynsmem); return; }

    float*         sBias = (float*)(dynsmem + BIAS_OFF);
    __nv_bfloat16* sAh   = (__nv_bfloat16*)(dynsmem + AH_OFF);
    __nv_bfloat16* sAl   = (__nv_bfloat16*)(dynsmem + AL_OFF);
    __nv_bfloat16* sBh   = (__nv_bfloat16*)(dynsmem + BH_OFF);
    __nv_bfloat16* sBl   = (__nv_bfloat16*)(dynsmem + BL_OFF);

    int b  = blockIdx.x >> 1;
    int t0 = (blockIdx.x & 1) << 7;
    if (t0 >= seq_lens[b]) return;

    int tid = threadIdx.x;

    for (int i = tid; i < GC; i += 256) sBias[i] = (i < 256) ? gb[i] : cb[i - 256];

    {
        int r = tid >> 1, half = tid & 1;
        int item = item_his[b * T_ + t0 + r];
        const float4* e4 = reinterpret_cast<const float4*>(emb + (size_t)item * D_ + half * 32);
        #pragma unroll
        for (int q = 0; q < 8; q++) {
            float4 v = e4[q];
            float f[4] = {v.x, v.y, v.z, v.w};
            int c0 = half * 32 + q * 4;
            #pragma unroll
            for (int i = 0; i < 2; i++) {
                uint32_t lo;
                uint32_t hi = split_pack(f[2*i], f[2*i+1], lo);
                *reinterpret_cast<uint32_t*>(&sAh[r * SA + c0 + 2*i]) = hi;
                *reinterpret_cast<uint32_t*>(&sAl[r * SA + c0 + 2*i]) = lo;
            }
        }
    }
    for (int idx = tid; idx < D_ * GC; idx += 256) {
        int k = idx / GC, n = idx - k * GC;
        float w = (n < 256) ? gk[k * 256 + n] : ck[k * 128 + (n - 256)];
        __nv_bfloat16 h = __float2bfloat16(w);
        sBh[n * SA + k] = h;
        sBl[n * SA + k] = __float2bfloat16(w - __bfloat162float(h));
    }
    __syncthreads();

    int wid = tid >> 5, lane = tid & 31;
    int gid = lane >> 2, tig = lane & 3;
    int m0 = wid * 16;

    uint32_t ah[4][4], al[4][4];
    #pragma unroll
    for (int ks = 0; ks < 4; ks++) {
        int c = ks * 16 + 2 * tig;
        ah[ks][0] = *reinterpret_cast<const uint32_t*>(&sAh[(m0+gid)   * SA + c]);
        ah[ks][1] = *reinterpret_cast<const uint32_t*>(&sAh[(m0+gid+8) * SA + c]);
        ah[ks][2] = *reinterpret_cast<const uint32_t*>(&sAh[(m0+gid)   * SA + c + 8]);
        ah[ks][3] = *reinterpret_cast<const uint32_t*>(&sAh[(m0+gid+8) * SA + c + 8]);
        al[ks][0] = *reinterpret_cast<const uint32_t*>(&sAl[(m0+gid)   * SA + c]);
        al[ks][1] = *reinterpret_cast<const uint32_t*>(&sAl[(m0+gid+8) * SA + c]);
        al[ks][2] = *reinterpret_cast<const uint32_t*>(&sAl[(m0+gid)   * SA + c + 8]);
        al[ks][3] = *reinterpret_cast<const uint32_t*>(&sAl[(m0+gid+8) * SA + c + 8]);
    }

    float* outbase = g_xproj + ((size_t)b * T_ + t0) * GC;

    for (int nt = 0; nt < 48; nt += 2) {
        float acc0[4] = {0.f, 0.f, 0.f, 0.f};
        float acc1[4] = {0.f, 0.f, 0.f, 0.f};
        #pragma unroll
        for (int ks = 0; ks < 4; ks++) {
            int c = ks * 16 + 2 * tig;
            int n0 = (nt * 8 + gid) * SA, n1 = ((nt + 1) * 8 + gid) * SA;
            uint32_t bh00 = *reinterpret_cast<const uint32_t*>(&sBh[n0 + c]);
            uint32_t bh01 = *reinterpret_cast<const uint32_t*>(&sBh[n0 + c + 8]);
            uint32_t bl00 = *reinterpret_cast<const uint32_t*>(&sBl[n0 + c]);
            uint32_t bl01 = *reinterpret_cast<const uint32_t*>(&sBl[n0 + c + 8]);
            uint32_t bh10 = *reinterpret_cast<const uint32_t*>(&sBh[n1 + c]);
            uint32_t bh11 = *reinterpret_cast<const uint32_t*>(&sBh[n1 + c + 8]);
            uint32_t bl10 = *reinterpret_cast<const uint32_t*>(&sBl[n1 + c]);
            uint32_t bl11 = *reinterpret_cast<const uint32_t*>(&sBl[n1 + c + 8]);
            mma16816(acc0, ah[ks], bh00, bh01);
            mma16816(acc1, ah[ks], bh10, bh11);
            mma16816(acc0, ah[ks], bl00, bl01);
            mma16816(acc1, ah[ks], bl10, bl11);
            mma16816(acc0, al[ks], bh00, bh01);
            mma16816(acc1, al[ks], bh10, bh11);
        }
        #pragma unroll
        for (int p = 0; p < 2; p++) {
            float* acc = p ? acc1 : acc0;
            int ncol = (nt + p) * 8 + 2 * tig;
            float2 bias = *reinterpret_cast<const float2*>(&sBias[ncol]);
            float2 o0 = {acc[0] + bias.x, acc[1] + bias.y};
            float2 o1 = {acc[2] + bias.x, acc[3] + bias.y};
            *reinterpret_cast<float2*>(outbase + (size_t)(m0 + gid)     * GC + ncol) = o0;
            *reinterpret_cast<float2*>(outbase + (size_t)(m0 + gid + 8) * GC + ncol) = o1;
        }
    }
}

// ---------------- Phase B: tensor-core GRU with [h_hi; h_lo] m-packing ----------------
// 128 CTAs x 8 rows, 512 threads. A rows 0-7 = hi, rows 8-15 = lo -> exact 4-term
// product in 2 MMAs per (nt,ks). Weight-hi frags in regs, weight-lo in smem.
static constexpr int OFF_BGL  = 0;        // uint2[32nt][8ks][32ln] 65536 B
static constexpr int OFF_BCL  = 65536;    // uint2[16][8][32]       32768 B
static constexpr int OFF_A    = 98304;    // u32[8ks][32ln][4]      4096 B
static constexpr int OFF_R    = 102400;   // u32[8ks][32ln][4]      4096 B
static constexpr int OFF_H    = 106496;   // f32[8][132]            4224 B
static constexpr int OFF_U    = 110720;
static constexpr int OFF_META = 114944;
static constexpr int G_SMEM   = 115072;
#define HS 132

__global__ void __launch_bounds__(512, 1) gru_mma_kernel(
    const int* __restrict__ seq_lens,
    const float* __restrict__ gk, const float* __restrict__ ck,
    float* __restrict__ out)
{
    extern __shared__ char dynsmem[];
    uint2* sBgL = (uint2*)(dynsmem + OFF_BGL);
    uint2* sBcL = (uint2*)(dynsmem + OFF_BCL);
    uint32_t* sA = (uint32_t*)(dynsmem + OFF_A);
    uint32_t* sR = (uint32_t*)(dynsmem + OFF_R);
    float* sH = (float*)(dynsmem + OFF_H);
    float* sU = (float*)(dynsmem + OFF_U);
    int* srow = (int*)(dynsmem + OFF_META);
    int* slen = srow + 8;

    int tid = threadIdx.x;
    int wid = tid >> 5, lane = tid & 31;
    int gid = lane >> 2, tig = lane & 3;
    int nt0 = 2 * wid, nt1 = nt0 + 1;

    // weight-lo fragments -> smem
    for (int idx = tid; idx < 32 * 8 * 32; idx += 512) {
        uint2 lo;
        frag_make(gk, 256, idx >> 8, (idx >> 5) & 7, idx & 31, lo);
        sBgL[idx] = lo;
    }
    for (int idx = tid; idx < 16 * 8 * 32; idx += 512) {
        uint2 lo;
        frag_make(ck, 128, idx >> 8, (idx >> 5) & 7, idx & 31, lo);
        sBcL[idx] = lo;
    }
    // weight-hi fragments -> registers
    uint2 BgH0[8], BgH1[8], BcH[8];
    #pragma unroll
    for (int ks = 0; ks < 8; ks++) {
        uint2 dump;
        BgH0[ks] = frag_make(gk, 256, nt0, ks, lane, dump);
        BgH1[ks] = frag_make(gk, 256, nt1, ks, lane, dump);
        BcH[ks]  = frag_make(ck, 128, wid, ks, lane, dump);
    }
    // zero state
    for (int i = tid; i < 1024; i += 512) { sA[i] = 0u; sR[i] = 0u; }
    for (int i = tid; i < 8 * HS; i += 512) { sH[i] = 0.0f; sU[i] = 0.0f; }
    if (tid < 8) {
        int row = g_order[blockIdx.x * 8 + tid];
        srow[tid] = row;
        slen[tid] = seq_lens[row];
    }
    __syncthreads();

    int maxlen = slen[0];
    int mylen  = slen[gid];
    int myxoff = srow[gid] * (T_ * GC);
    int cA0 = 16 * wid + 2 * tig;
    int cA1 = cA0 + 8;
    int j0  = 8 * wid + 2 * tig;
    bool isR = (wid < 8);
    int rhOff = (wid * 32 + lane) * 4;                              // wid<8: ks=wid
    int ahOff = ((j0 >> 4) * 32 + lane) * 4 + ((wid & 1) ? 2 : 0);  // hi at +0, lo at +1

    // preload x-projections for t = 0
    float2 xg0 = make_float2(0.f, 0.f), xg1 = make_float2(0.f, 0.f), xc = make_float2(0.f, 0.f);
    if (0 < mylen) {
        xg0 = *reinterpret_cast<const float2*>(&g_xproj[myxoff + cA0]);
        xg1 = *reinterpret_cast<const float2*>(&g_xproj[myxoff + cA1]);
        xc  = *reinterpret_cast<const float2*>(&g_xproj[myxoff + 256 + j0]);
    }

    for (int t = 0; t < maxlen; t++) {
        // prefetch t+1 (consumed next iteration -> full-step DRAM cover)
        float2 xg0n = make_float2(0.f, 0.f), xg1n = make_float2(0.f, 0.f);
        float2 xcn  = make_float2(0.f, 0.f);
        if (t + 1 < mylen) {
            int bn = myxoff + (t + 1) * GC;
            xg0n = *reinterpret_cast<const float2*>(&g_xproj[bn + cA0]);
            xg1n = *reinterpret_cast<const float2*>(&g_xproj[bn + cA1]);
            xcn  = *reinterpret_cast<const float2*>(&g_xproj[bn + 256 + j0]);
        }
        bool act = (t < mylen);

        // ---- gate MMA: A=[h_hi;h_lo], 4 independent 8-deep chains ----
        float d1a[4] = {0.f,0.f,0.f,0.f}, d1b[4] = {0.f,0.f,0.f,0.f};
        float d2a[4] = {0.f,0.f,0.f,0.f}, d2b[4] = {0.f,0.f,0.f,0.f};
        #pragma unroll
        for (int ks = 0; ks < 8; ks++) {
            uint4 a4 = *reinterpret_cast<const uint4*>(&sA[(ks * 32 + lane) * 4]);
            uint2 bl0 = sBgL[(nt0 * 8 + ks) * 32 + lane];
            uint2 bl1 = sBgL[(nt1 * 8 + ks) * 32 + lane];
            const uint32_t* a = reinterpret_cast<const uint32_t*>(&a4);
            mma16816(d1a, a, BgH0[ks].x, BgH0[ks].y);
            mma16816(d1b, a, BgH1[ks].x, BgH1[ks].y);
            mma16816(d2a, a, bl0.x, bl0.y);
            mma16816(d2b, a, bl1.x, bl1.y);
        }
        // row gid result = (hi rows: d[0,1]) + (lo rows: d[2,3]) over both passes
        float s0 = sigmoidf_(d1a[0] + d1a[2] + d2a[0] + d2a[2] + xg0.x);
        float s1 = sigmoidf_(d1a[1] + d1a[3] + d2a[1] + d2a[3] + xg0.y);
        float s2 = sigmoidf_(d1b[0] + d1b[2] + d2b[0] + d2b[2] + xg1.x);
        float s3 = sigmoidf_(d1b[1] + d1b[3] + d2b[1] + d2b[3] + xg1.y);
        if (isR) {
            float2 h01 = *reinterpret_cast<const float2*>(&sH[gid * HS + cA0]);
            float2 h23 = *reinterpret_cast<const float2*>(&sH[gid * HS + cA1]);
            uint32_t lo;
            uint32_t hi = split_pack(s0 * h01.x, s1 * h01.y, lo);
            sR[rhOff]     = hi; sR[rhOff + 1] = lo;
            hi = split_pack(s2 * h23.x, s3 * h23.y, lo);
            sR[rhOff + 2] = hi; sR[rhOff + 3] = lo;
        } else {
            *reinterpret_cast<float2*>(&sU[gid * HS + cA0 - 128]) = make_float2(s0, s1);
            *reinterpret_cast<float2*>(&sU[gid * HS + cA1 - 128]) = make_float2(s2, s3);
        }
        __syncthreads();

        float2 uu   = *reinterpret_cast<const float2*>(&sU[gid * HS + j0]);
        float2 hold = *reinterpret_cast<const float2*>(&sH[gid * HS + j0]);

        // ---- cand MMA: A=[rh_hi;rh_lo], 2 independent 8-deep chains ----
        float c1[4] = {0.f,0.f,0.f,0.f}, c2[4] = {0.f,0.f,0.f,0.f};
        #pragma unroll
        for (int ks = 0; ks < 8; ks++) {
            uint4 a4 = *reinterpret_cast<const uint4*>(&sR[(ks * 32 + lane) * 4]);
            uint2 bl = sBcL[(wid * 8 + ks) * 32 + lane];
            const uint32_t* a = reinterpret_cast<const uint32_t*>(&a4);
            mma16816(c1, a, BcH[ks].x, BcH[ks].y);
            mma16816(c2, a, bl.x, bl.y);
        }

        // ---- update (this thread owns h[gid][j0..j0+1]) ----
        if (act) {
            float cc0 = tanhf_(c1[0] + c1[2] + c2[0] + c2[2] + xc.x);
            float cc1 = tanhf_(c1[1] + c1[3] + c2[1] + c2[3] + xc.y);
            float hn0 = uu.x * hold.x + (1.0f - uu.x) * cc0;
            float hn1 = uu.y * hold.y + (1.0f - uu.y) * cc1;
            *reinterpret_cast<float2*>(&sH[gid * HS + j0]) = make_float2(hn0, hn1);
            uint32_t lo;
            uint32_t hi = split_pack(hn0, hn1, lo);
            sA[ahOff]     = hi;   // row gid   (h_hi)
            sA[ahOff + 1] = lo;   // row gid+8 (h_lo)
        }
        __syncthreads();

        xg0 = xg0n; xg1 = xg1n; xc = xcn;
    }

    // output: thread owns h[gid][j0..j0+1]
    float2 hv = *reinterpret_cast<const float2*>(&sH[gid * HS + j0]);
    *reinterpret_cast<float2*>(&out[(size_t)srow[gid] * H_ + j0]) = hv;
}

// ---------------- launch ----------------
extern "C" void kernel_launch(void* const* d_in, const int* in_sizes, int n_in,
                              void* d_out, int out_size) {
    const int*   item_his = (const int*)  d_in[0];
    const int*   seq_lens = (const int*)  d_in[1];
    const float* emb      = (const float*)d_in[2];
    const float* gk       = (const float*)d_in[3];
    const float* gb       = (const float*)d_in[4];
    const float* ck       = (const float*)d_in[5];
    const float* cb       = (const float*)d_in[6];
    float*       out      = (float*)d_out;

    cudaFuncSetAttribute(xproj_mma_kernel, cudaFuncAttributeMaxDynamicSharedMemorySize, PA_SMEM);
    cudaFuncSetAttribute(gru_mma_kernel,   cudaFuncAttributeMaxDynamicSharedMemorySize, G_SMEM);

    xproj_mma_kernel<<<2049, 256, PA_SMEM>>>(item_his, seq_lens, emb, gk, gb, ck, cb);
    gru_mma_kernel<<<B_ / 8, 512, G_SMEM>>>(seq_lens, gk, ck, out);
}

// round 13
// speedup vs baseline: 2.2568x; 1.0726x over previous
#include <cuda_runtime.h>
#include <cuda_bf16.h>
#include <cstdint>

#define B_    1024
#define T_    256
#define D_    64
#define H_    128
#define GC    384

__device__ float g_xproj[(size_t)B_ * T_ * GC];
__device__ int   g_order[B_];
__device__ uint2 g_bfxH[6144];   // Phase-A W fragments (hi), [48nt][4ks][32ln]
__device__ uint2 g_bfxL[6144];   // (lo)

__device__ __forceinline__ float sigmoidf_(float x) {
    return __fdividef(1.0f, 1.0f + __expf(-x));
}
__device__ __forceinline__ float tanhf_(float x) {
    return 1.0f - __fdividef(2.0f, __expf(2.0f * x) + 1.0f);
}

// ---------------- warp-level bf16 MMA ----------------
__device__ __forceinline__ void mma16816(float* d, const uint32_t* a, uint32_t b0, uint32_t b1) {
    asm volatile(
        "mma.sync.aligned.m16n8k16.row.col.f32.bf16.bf16.f32 "
        "{%0,%1,%2,%3}, {%4,%5,%6,%7}, {%8,%9}, {%0,%1,%2,%3};"
        : "+f"(d[0]), "+f"(d[1]), "+f"(d[2]), "+f"(d[3])
        : "r"(a[0]), "r"(a[1]), "r"(a[2]), "r"(a[3]), "r"(b0), "r"(b1));
}

__device__ __forceinline__ uint32_t split_pack(float x, float y, uint32_t& lo) {
    __nv_bfloat16 hx = __float2bfloat16(x), hy = __float2bfloat16(y);
    __nv_bfloat162 hp; hp.x = hx; hp.y = hy;
    __nv_bfloat162 lp;
    lp.x = __float2bfloat16(x - __bfloat162float(hx));
    lp.y = __float2bfloat16(y - __bfloat162float(hy));
    lo = *reinterpret_cast<uint32_t*>(&lp);
    return *reinterpret_cast<uint32_t*>(&hp);
}

// B-fragment builder for RECURRENT W rows (64+k)
__device__ __forceinline__ uint2 frag_make(const float* W, int ldn, int nt, int ks, int ln,
                                           uint2& lo) {
    int g = ln >> 2, tg = ln & 3;
    int n = 8 * nt + g, k0 = 16 * ks + 2 * tg;
    uint32_t l0, l1;
    uint32_t h0 = split_pack(W[(64 + k0)     * ldn + n], W[(64 + k0 + 1) * ldn + n], l0);
    uint32_t h1 = split_pack(W[(64 + k0 + 8) * ldn + n], W[(64 + k0 + 9) * ldn + n], l1);
    lo = make_uint2(l0, l1);
    return make_uint2(h0, h1);
}

// B-fragment builder for X-PART W rows (0..63), combined 384-col space
__device__ __forceinline__ uint2 frag_make_x(const float* gkp, const float* ckp,
                                             int nt, int ks, int ln, uint2& lo) {
    int g = ln >> 2, tg = ln & 3;
    int n = 8 * nt + g, k0 = 16 * ks + 2 * tg;
    float w00, w01, w10, w11;
    if (n < 256) {
        w00 = gkp[k0 * 256 + n];       w01 = gkp[(k0 + 1) * 256 + n];
        w10 = gkp[(k0 + 8) * 256 + n]; w11 = gkp[(k0 + 9) * 256 + n];
    } else {
        int m = n - 256;
        w00 = ckp[k0 * 128 + m];       w01 = ckp[(k0 + 1) * 128 + m];
        w10 = ckp[(k0 + 8) * 128 + m]; w11 = ckp[(k0 + 9) * 128 + m];
    }
    uint32_t l0, l1;
    uint32_t h0 = split_pack(w00, w01, l0);
    uint32_t h1 = split_pack(w10, w11, l1);
    lo = make_uint2(l0, l1);
    return make_uint2(h0, h1);
}

// ---------------- setup: sort (block 0) + Phase-A weight frag split (block 1) ----------
__global__ void setup_kernel(const int* __restrict__ seq_lens,
                             const float* __restrict__ gk, const float* __restrict__ ck) {
    int tid = threadIdx.x;
    if (blockIdx.x == 0) {
        __shared__ int hist[T_];
        __shared__ int offs[T_];
        for (int i = tid; i < T_; i += 256) hist[i] = 0;
        __syncthreads();
        for (int i = tid; i < B_; i += 256) atomicAdd(&hist[T_ - 1 - seq_lens[i]], 1);
        __syncthreads();
        if (tid == 0) { int s = 0; for (int k = 0; k < T_; k++) { offs[k] = s; s += hist[k]; } }
        __syncthreads();
        for (int i = tid; i < T_; i += 256) hist[i] = 0;
        __syncthreads();
        for (int i = tid; i < B_; i += 256) {
            int key = T_ - 1 - seq_lens[i];
            g_order[offs[key] + atomicAdd(&hist[key], 1)] = i;
        }
    } else {
        for (int idx = tid; idx < 6144; idx += 256) {
            int nt = idx >> 7, ks = (idx >> 5) & 3, ln = idx & 31;
            uint2 lo;
            uint2 hi = frag_make_x(gk, ck, nt, ks, ln, lo);
            g_bfxH[idx] = hi;
            g_bfxL[idx] = lo;
        }
    }
}

// ---------------- Phase A v2: B-frags streamed from global, 3 CTAs/SM ----------------
static constexpr int BIAS_OFF = 0;        // 384 f32
static constexpr int AH_OFF   = 1536;     // [128][72] bf16
static constexpr int AL_OFF   = 19968;
static constexpr int PA_SMEM  = 38400;
#define SA 72

__global__ void __launch_bounds__(256, 3) xproj_mma_kernel(
    const int* __restrict__ item_his, const int* __restrict__ seq_lens,
    const float* __restrict__ emb,
    const float* __restrict__ gb, const float* __restrict__ cb)
{
    extern __shared__ char dynsmem[];
    float*         sBias = (float*)(dynsmem + BIAS_OFF);
    __nv_bfloat16* sAh   = (__nv_bfloat16*)(dynsmem + AH_OFF);
    __nv_bfloat16* sAl   = (__nv_bfloat16*)(dynsmem + AL_OFF);

    int b  = blockIdx.x >> 1;
    int t0 = (blockIdx.x & 1) << 7;
    if (t0 >= seq_lens[b]) return;

    int tid = threadIdx.x;

    for (int i = tid; i < GC; i += 256) sBias[i] = (i < 256) ? gb[i] : cb[i - 256];

    // A gather: 2 threads per row, each 32 cols; split bf16 hi/lo
    {
        int r = tid >> 1, half = tid & 1;
        int item = item_his[b * T_ + t0 + r];
        const float4* e4 = reinterpret_cast<const float4*>(emb + (size_t)item * D_ + half * 32);
        #pragma unroll
        for (int q = 0; q < 8; q++) {
            float4 v = e4[q];
            float f[4] = {v.x, v.y, v.z, v.w};
            int c0 = half * 32 + q * 4;
            #pragma unroll
            for (int i = 0; i < 2; i++) {
                uint32_t lo;
                uint32_t hi = split_pack(f[2*i], f[2*i+1], lo);
                *reinterpret_cast<uint32_t*>(&sAh[r * SA + c0 + 2*i]) = hi;
                *reinterpret_cast<uint32_t*>(&sAl[r * SA + c0 + 2*i]) = lo;
            }
        }
    }
    __syncthreads();

    int wid = tid >> 5, lane = tid & 31;
    int gid = lane >> 2, tig = lane & 3;
    int m0 = wid * 16;

    // register-cache A fragments for this warp's m-tile
    uint32_t ah[4][4], al[4][4];
    #pragma unroll
    for (int ks = 0; ks < 4; ks++) {
        int c = ks * 16 + 2 * tig;
        ah[ks][0] = *reinterpret_cast<const uint32_t*>(&sAh[(m0+gid)   * SA + c]);
        ah[ks][1] = *reinterpret_cast<const uint32_t*>(&sAh[(m0+gid+8) * SA + c]);
        ah[ks][2] = *reinterpret_cast<const uint32_t*>(&sAh[(m0+gid)   * SA + c + 8]);
        ah[ks][3] = *reinterpret_cast<const uint32_t*>(&sAh[(m0+gid+8) * SA + c + 8]);
        al[ks][0] = *reinterpret_cast<const uint32_t*>(&sAl[(m0+gid)   * SA + c]);
        al[ks][1] = *reinterpret_cast<const uint32_t*>(&sAl[(m0+gid+8) * SA + c]);
        al[ks][2] = *reinterpret_cast<const uint32_t*>(&sAl[(m0+gid)   * SA + c + 8]);
        al[ks][3] = *reinterpret_cast<const uint32_t*>(&sAl[(m0+gid+8) * SA + c + 8]);
    }

    float* outbase = g_xproj + ((size_t)b * T_ + t0) * GC;

    const uint2* __restrict__ fH = g_bfxH;
    const uint2* __restrict__ fL = g_bfxL;

    for (int nt = 0; nt < 48; nt += 2) {
        float acc0[4] = {0.f, 0.f, 0.f, 0.f};
        float acc1[4] = {0.f, 0.f, 0.f, 0.f};
        #pragma unroll
        for (int ks = 0; ks < 4; ks++) {
            uint2 bh0 = __ldg(&fH[(nt       * 4 + ks) * 32 + lane]);
            uint2 bl0 = __ldg(&fL[(nt       * 4 + ks) * 32 + lane]);
            uint2 bh1 = __ldg(&fH[((nt + 1) * 4 + ks) * 32 + lane]);
            uint2 bl1 = __ldg(&fL[((nt + 1) * 4 + ks) * 32 + lane]);
            mma16816(acc0, ah[ks], bh0.x, bh0.y);
            mma16816(acc1, ah[ks], bh1.x, bh1.y);
            mma16816(acc0, ah[ks], bl0.x, bl0.y);
            mma16816(acc1, ah[ks], bl1.x, bl1.y);
            mma16816(acc0, al[ks], bh0.x, bh0.y);
            mma16816(acc1, al[ks], bh1.x, bh1.y);
        }
        #pragma unroll
        for (int p = 0; p < 2; p++) {
            float* acc = p ? acc1 : acc0;
            int ncol = (nt + p) * 8 + 2 * tig;
            float2 bias = *reinterpret_cast<const float2*>(&sBias[ncol]);
            float2 o0 = {acc[0] + bias.x, acc[1] + bias.y};
            float2 o1 = {acc[2] + bias.x, acc[3] + bias.y};
            *reinterpret_cast<float2*>(outbase + (size_t)(m0 + gid)     * GC + ncol) = o0;
            *reinterpret_cast<float2*>(outbase + (size_t)(m0 + gid + 8) * GC + ncol) = o1;
        }
    }
}

// ---------------- Phase B: tensor-core GRU with [h_hi; h_lo] m-packing (r12 winner) ----
static constexpr int OFF_BGL  = 0;        // uint2[32nt][8ks][32ln] 65536 B
static constexpr int OFF_BCL  = 65536;    // uint2[16][8][32]       32768 B
static constexpr int OFF_A    = 98304;    // u32[8ks][32ln][4]      4096 B
static constexpr int OFF_R    = 102400;
static constexpr int OFF_H    = 106496;   // f32[8][132]            4224 B
static constexpr int OFF_U    = 110720;
static constexpr int OFF_META = 114944;
static constexpr int G_SMEM   = 115072;
#define HS 132

__global__ void __launch_bounds__(512, 1) gru_mma_kernel(
    const int* __restrict__ seq_lens,
    const float* __restrict__ gk, const float* __restrict__ ck,
    float* __restrict__ out)
{
    extern __shared__ char dynsmem[];
    uint2* sBgL = (uint2*)(dynsmem + OFF_BGL);
    uint2* sBcL = (uint2*)(dynsmem + OFF_BCL);
    uint32_t* sA = (uint32_t*)(dynsmem + OFF_A);
    uint32_t* sR = (uint32_t*)(dynsmem + OFF_R);
    float* sH = (float*)(dynsmem + OFF_H);
    float* sU = (float*)(dynsmem + OFF_U);
    int* srow = (int*)(dynsmem + OFF_META);
    int* slen = srow + 8;

    int tid = threadIdx.x;
    int wid = tid >> 5, lane = tid & 31;
    int gid = lane >> 2, tig = lane & 3;
    int nt0 = 2 * wid, nt1 = nt0 + 1;

    // weight-lo fragments -> smem
    for (int idx = tid; idx < 32 * 8 * 32; idx += 512) {
        uint2 lo;
        frag_make(gk, 256, idx >> 8, (idx >> 5) & 7, idx & 31, lo);
        sBgL[idx] = lo;
    }
    for (int idx = tid; idx < 16 * 8 * 32; idx += 512) {
        uint2 lo;
        frag_make(ck, 128, idx >> 8, (idx >> 5) & 7, idx & 31, lo);
        sBcL[idx] = lo;
    }
    // weight-hi fragments -> registers
    uint2 BgH0[8], BgH1[8], BcH[8];
    #pragma unroll
    for (int ks = 0; ks < 8; ks++) {
        uint2 dump;
        BgH0[ks] = frag_make(gk, 256, nt0, ks, lane, dump);
        BgH1[ks] = frag_make(gk, 256, nt1, ks, lane, dump);
        BcH[ks]  = frag_make(ck, 128, wid, ks, lane, dump);
    }
    // zero state
    for (int i = tid; i < 1024; i += 512) { sA[i] = 0u; sR[i] = 0u; }
    for (int i = tid; i < 8 * HS; i += 512) { sH[i] = 0.0f; sU[i] = 0.0f; }
    if (tid < 8) {
        int row = g_order[blockIdx.x * 8 + tid];
        srow[tid] = row;
        slen[tid] = seq_lens[row];
    }
    __syncthreads();

    int maxlen = slen[0];
    int mylen  = slen[gid];
    int myxoff = srow[gid] * (T_ * GC);
    int cA0 = 16 * wid + 2 * tig;
    int cA1 = cA0 + 8;
    int j0  = 8 * wid + 2 * tig;
    bool isR = (wid < 8);
    int rhOff = (wid * 32 + lane) * 4;
    int ahOff = ((j0 >> 4) * 32 + lane) * 4 + ((wid & 1) ? 2 : 0);

    // preload x-projections for t = 0
    float2 xg0 = make_float2(0.f, 0.f), xg1 = make_float2(0.f, 0.f), xc = make_float2(0.f, 0.f);
    if (0 < mylen) {
        xg0 = *reinterpret_cast<const float2*>(&g_xproj[myxoff + cA0]);
        xg1 = *reinterpret_cast<const float2*>(&g_xproj[myxoff + cA1]);
        xc  = *reinterpret_cast<const float2*>(&g_xproj[myxoff + 256 + j0]);
    }

    for (int t = 0; t < maxlen; t++) {
        float2 xg0n = make_float2(0.f, 0.f), xg1n = make_float2(0.f, 0.f);
        float2 xcn  = make_float2(0.f, 0.f);
        if (t + 1 < mylen) {
            int bn = myxoff + (t + 1) * GC;
            xg0n = *reinterpret_cast<const float2*>(&g_xproj[bn + cA0]);
            xg1n = *reinterpret_cast<const float2*>(&g_xproj[bn + cA1]);
            xcn  = *reinterpret_cast<const float2*>(&g_xproj[bn + 256 + j0]);
        }
        bool act = (t < mylen);

        // ---- gate MMA: A=[h_hi;h_lo], 4 independent 8-deep chains ----
        float d1a[4] = {0.f,0.f,0.f,0.f}, d1b[4] = {0.f,0.f,0.f,0.f};
        float d2a[4] = {0.f,0.f,0.f,0.f}, d2b[4] = {0.f,0.f,0.f,0.f};
        #pragma unroll
        for (int ks = 0; ks < 8; ks++) {
            uint4 a4 = *reinterpret_cast<const uint4*>(&sA[(ks * 32 + lane) * 4]);
            uint2 bl0 = sBgL[(nt0 * 8 + ks) * 32 + lane];
            uint2 bl1 = sBgL[(nt1 * 8 + ks) * 32 + lane];
            const uint32_t* a = reinterpret_cast<const uint32_t*>(&a4);
            mma16816(d1a, a, BgH0[ks].x, BgH0[ks].y);
            mma16816(d1b, a, BgH1[ks].x, BgH1[ks].y);
            mma16816(d2a, a, bl0.x, bl0.y);
            mma16816(d2b, a, bl1.x, bl1.y);
        }
        float s0 = sigmoidf_(d1a[0] + d1a[2] + d2a[0] + d2a[2] + xg0.x);
        float s1 = sigmoidf_(d1a[1] + d1a[3] + d2a[1] + d2a[3] + xg0.y);
        float s2 = sigmoidf_(d1b[0] + d1b[2] + d2b[0] + d2b[2] + xg1.x);
        float s3 = sigmoidf_(d1b[1] + d1b[3] + d2b[1] + d2b[3] + xg1.y);
        if (isR) {
            float2 h01 = *reinterpret_cast<const float2*>(&sH[gid * HS + cA0]);
            float2 h23 = *reinterpret_cast<const float2*>(&sH[gid * HS + cA1]);
            uint32_t lo;
            uint32_t hi = split_pack(s0 * h01.x, s1 * h01.y, lo);
            sR[rhOff]     = hi; sR[rhOff + 1] = lo;
            hi = split_pack(s2 * h23.x, s3 * h23.y, lo);
            sR[rhOff + 2] = hi; sR[rhOff + 3] = lo;
        } else {
            *reinterpret_cast<float2*>(&sU[gid * HS + cA0 - 128]) = make_float2(s0, s1);
            *reinterpret_cast<float2*>(&sU[gid * HS + cA1 - 128]) = make_float2(s2, s3);
        }
        __syncthreads();

        float2 uu   = *reinterpret_cast<const float2*>(&sU[gid * HS + j0]);
        float2 hold = *reinterpret_cast<const float2*>(&sH[gid * HS + j0]);

        // ---- cand MMA: A=[rh_hi;rh_lo], 2 independent 8-deep chains ----
        float c1[4] = {0.f,0.f,0.f,0.f}, c2[4] = {0.f,0.f,0.f,0.f};
        #pragma unroll
        for (int ks = 0; ks < 8; ks++) {
            uint4 a4 = *reinterpret_cast<const uint4*>(&sR[(ks * 32 + lane) * 4]);
            uint2 bl = sBcL[(wid * 8 + ks) * 32 + lane];
            const uint32_t* a = reinterpret_cast<const uint32_t*>(&a4);
            mma16816(c1, a, BcH[ks].x, BcH[ks].y);
            mma16816(c2, a, bl.x, bl.y);
        }

        // ---- update (this thread owns h[gid][j0..j0+1]) ----
        if (act) {
            float cc0 = tanhf_(c1[0] + c1[2] + c2[0] + c2[2] + xc.x);
            float cc1 = tanhf_(c1[1] + c1[3] + c2[1] + c2[3] + xc.y);
            float hn0 = uu.x * hold.x + (1.0f - uu.x) * cc0;
            float hn1 = uu.y * hold.y + (1.0f - uu.y) * cc1;
            *reinterpret_cast<float2*>(&sH[gid * HS + j0]) = make_float2(hn0, hn1);
            uint32_t lo;
            uint32_t hi = split_pack(hn0, hn1, lo);
            sA[ahOff]     = hi;
            sA[ahOff + 1] = lo;
        }
        __syncthreads();

        xg0 = xg0n; xg1 = xg1n; xc = xcn;
    }

    float2 hv = *reinterpret_cast<const float2*>(&sH[gid * HS + j0]);
    *reinterpret_cast<float2*>(&out[(size_t)srow[gid] * H_ + j0]) = hv;
}

// ---------------- launch ----------------
extern "C" void kernel_launch(void* const* d_in, const int* in_sizes, int n_in,
                              void* d_out, int out_size) {
    const int*   item_his = (const int*)  d_in[0];
    const int*   seq_lens = (const int*)  d_in[1];
    const float* emb      = (const float*)d_in[2];
    const float* gk       = (const float*)d_in[3];
    const float* gb       = (const float*)d_in[4];
    const float* ck       = (const float*)d_in[5];
    const float* cb       = (const float*)d_in[6];
    float*       out      = (float*)d_out;

    cudaFuncSetAttribute(xproj_mma_kernel, cudaFuncAttributeMaxDynamicSharedMemorySize, PA_SMEM);
    cudaFuncSetAttribute(gru_mma_kernel,   cudaFuncAttributeMaxDynamicSharedMemorySize, G_SMEM);

    setup_kernel<<<2, 256>>>(seq_lens, gk, ck);
    xproj_mma_kernel<<<B_ * 2, 256, PA_SMEM>>>(item_his, seq_lens, emb, gb, cb);
    gru_mma_kernel<<<B_ / 8, 512, G_SMEM>>>(seq_lens, gk, ck, out);
}

// round 14
// speedup vs baseline: 2.5287x; 1.1205x over previous
#include <cuda_runtime.h>
#include <cuda_bf16.h>
#include <cstdint>

#define B_    1024
#define T_    256
#define D_    64
#define H_    128
#define GC    384

__device__ float g_xproj[(size_t)B_ * T_ * GC];
__device__ int   g_order[B_];
__device__ uint2 g_bfxH[6144];   // Phase-A W fragments (hi), [48nt][4ks][32ln]
__device__ uint2 g_bfxL[6144];   // (lo)

__device__ __forceinline__ float sigmoidf_(float x) {
    return __fdividef(1.0f, 1.0f + __expf(-x));
}
__device__ __forceinline__ float tanhf_(float x) {
    return 1.0f - __fdividef(2.0f, __expf(2.0f * x) + 1.0f);
}

// ---------------- warp-level bf16 MMA ----------------
__device__ __forceinline__ void mma16816(float* d, const uint32_t* a, uint32_t b0, uint32_t b1) {
    asm volatile(
        "mma.sync.aligned.m16n8k16.row.col.f32.bf16.bf16.f32 "
        "{%0,%1,%2,%3}, {%4,%5,%6,%7}, {%8,%9}, {%0,%1,%2,%3};"
        : "+f"(d[0]), "+f"(d[1]), "+f"(d[2]), "+f"(d[3])
        : "r"(a[0]), "r"(a[1]), "r"(a[2]), "r"(a[3]), "r"(b0), "r"(b1));
}

__device__ __forceinline__ uint32_t split_pack(float x, float y, uint32_t& lo) {
    __nv_bfloat16 hx = __float2bfloat16(x), hy = __float2bfloat16(y);
    __nv_bfloat162 hp; hp.x = hx; hp.y = hy;
    __nv_bfloat162 lp;
    lp.x = __float2bfloat16(x - __bfloat162float(hx));
    lp.y = __float2bfloat16(y - __bfloat162float(hy));
    lo = *reinterpret_cast<uint32_t*>(&lp);
    return *reinterpret_cast<uint32_t*>(&hp);
}

// B-fragment builder for RECURRENT W rows (64+k)
__device__ __forceinline__ uint2 frag_make(const float* W, int ldn, int nt, int ks, int ln,
                                           uint2& lo) {
    int g = ln >> 2, tg = ln & 3;
    int n = 8 * nt + g, k0 = 16 * ks + 2 * tg;
    uint32_t l0, l1;
    uint32_t h0 = split_pack(W[(64 + k0)     * ldn + n], W[(64 + k0 + 1) * ldn + n], l0);
    uint32_t h1 = split_pack(W[(64 + k0 + 8) * ldn + n], W[(64 + k0 + 9) * ldn + n], l1);
    lo = make_uint2(l0, l1);
    return make_uint2(h0, h1);
}

// B-fragment builder for X-PART W rows (0..63), combined 384-col space
__device__ __forceinline__ uint2 frag_make_x(const float* gkp, const float* ckp,
                                             int nt, int ks, int ln, uint2& lo) {
    int g = ln >> 2, tg = ln & 3;
    int n = 8 * nt + g, k0 = 16 * ks + 2 * tg;
    float w00, w01, w10, w11;
    if (n < 256) {
        w00 = gkp[k0 * 256 + n];       w01 = gkp[(k0 + 1) * 256 + n];
        w10 = gkp[(k0 + 8) * 256 + n]; w11 = gkp[(k0 + 9) * 256 + n];
    } else {
        int m = n - 256;
        w00 = ckp[k0 * 128 + m];       w01 = ckp[(k0 + 1) * 128 + m];
        w10 = ckp[(k0 + 8) * 128 + m]; w11 = ckp[(k0 + 9) * 128 + m];
    }
    uint32_t l0, l1;
    uint32_t h0 = split_pack(w00, w01, l0);
    uint32_t h1 = split_pack(w10, w11, l1);
    lo = make_uint2(l0, l1);
    return make_uint2(h0, h1);
}

// ---------------- setup: sort (block 0) + Phase-A weight frag split (block 1) ----------
__global__ void setup_kernel(const int* __restrict__ seq_lens,
                             const float* __restrict__ gk, const float* __restrict__ ck) {
    int tid = threadIdx.x;
    if (blockIdx.x == 0) {
        __shared__ int hist[T_];
        __shared__ int offs[T_];
        for (int i = tid; i < T_; i += 256) hist[i] = 0;
        __syncthreads();
        for (int i = tid; i < B_; i += 256) atomicAdd(&hist[T_ - 1 - seq_lens[i]], 1);
        __syncthreads();
        if (tid == 0) { int s = 0; for (int k = 0; k < T_; k++) { offs[k] = s; s += hist[k]; } }
        __syncthreads();
        for (int i = tid; i < T_; i += 256) hist[i] = 0;
        __syncthreads();
        for (int i = tid; i < B_; i += 256) {
            int key = T_ - 1 - seq_lens[i];
            g_order[offs[key] + atomicAdd(&hist[key], 1)] = i;
        }
    } else {
        for (int idx = tid; idx < 6144; idx += 256) {
            int nt = idx >> 7, ks = (idx >> 5) & 3, ln = idx & 31;
            uint2 lo;
            uint2 hi = frag_make_x(gk, ck, nt, ks, ln, lo);
            g_bfxH[idx] = hi;
            g_bfxL[idx] = lo;
        }
    }
}

// ---------------- Phase A v3: x in plain bf16 (2-pass), per-warp len skip --------------
static constexpr int BIAS_OFF = 0;        // 384 f32
static constexpr int AH_OFF   = 1536;     // [128][72] bf16
static constexpr int PA_SMEM  = 20096;
#define SA 72

__global__ void __launch_bounds__(256, 3) xproj_mma_kernel(
    const int* __restrict__ item_his, const int* __restrict__ seq_lens,
    const float* __restrict__ emb,
    const float* __restrict__ gb, const float* __restrict__ cb)
{
    extern __shared__ char dynsmem[];
    float*         sBias = (float*)(dynsmem + BIAS_OFF);
    __nv_bfloat16* sAh   = (__nv_bfloat16*)(dynsmem + AH_OFF);

    int b  = blockIdx.x >> 1;
    int t0 = (blockIdx.x & 1) << 7;
    int len = seq_lens[b];
    if (t0 >= len) return;
    int mrows = len - t0;   // valid rows in this tile (1..128)

    int tid = threadIdx.x;

    for (int i = tid; i < GC; i += 256) sBias[i] = (i < 256) ? gb[i] : cb[i - 256];

    // A gather: 2 threads per row, each 32 cols; plain bf16 (x_lo dropped: err ~4e-5)
    {
        int r = tid >> 1, half = tid & 1;
        int item = item_his[b * T_ + t0 + r];
        const float4* e4 = reinterpret_cast<const float4*>(emb + (size_t)item * D_ + half * 32);
        #pragma unroll
        for (int q = 0; q < 8; q += 2) {
            float4 v0 = e4[q], v1 = e4[q + 1];
            __nv_bfloat162 p[4];
            p[0] = __nv_bfloat162(__float2bfloat16(v0.x), __float2bfloat16(v0.y));
            p[1] = __nv_bfloat162(__float2bfloat16(v0.z), __float2bfloat16(v0.w));
            p[2] = __nv_bfloat162(__float2bfloat16(v1.x), __float2bfloat16(v1.y));
            p[3] = __nv_bfloat162(__float2bfloat16(v1.z), __float2bfloat16(v1.w));
            int c0 = half * 32 + q * 4;
            *reinterpret_cast<uint4*>(&sAh[r * SA + c0]) = *reinterpret_cast<uint4*>(p);
        }
    }
    __syncthreads();

    int wid = tid >> 5, lane = tid & 31;
    int gid = lane >> 2, tig = lane & 3;
    int m0 = wid * 16;

    // skip whole m-tile past sequence end (rows never read by gru; no syncs below)
    if (m0 >= mrows) return;

    // register-cache A fragments for this warp's m-tile
    uint32_t ah[4][4];
    #pragma unroll
    for (int ks = 0; ks < 4; ks++) {
        int c = ks * 16 + 2 * tig;
        ah[ks][0] = *reinterpret_cast<const uint32_t*>(&sAh[(m0+gid)   * SA + c]);
        ah[ks][1] = *reinterpret_cast<const uint32_t*>(&sAh[(m0+gid+8) * SA + c]);
        ah[ks][2] = *reinterpret_cast<const uint32_t*>(&sAh[(m0+gid)   * SA + c + 8]);
        ah[ks][3] = *reinterpret_cast<const uint32_t*>(&sAh[(m0+gid+8) * SA + c + 8]);
    }

    float* outbase = g_xproj + ((size_t)b * T_ + t0) * GC;

    const uint2* __restrict__ fH = g_bfxH;
    const uint2* __restrict__ fL = g_bfxL;

    for (int nt = 0; nt < 48; nt += 2) {
        float acc0[4] = {0.f, 0.f, 0.f, 0.f};
        float acc1[4] = {0.f, 0.f, 0.f, 0.f};
        #pragma unroll
        for (int ks = 0; ks < 4; ks++) {
            uint2 bh0 = __ldg(&fH[(nt       * 4 + ks) * 32 + lane]);
            uint2 bl0 = __ldg(&fL[(nt       * 4 + ks) * 32 + lane]);
            uint2 bh1 = __ldg(&fH[((nt + 1) * 4 + ks) * 32 + lane]);
            uint2 bl1 = __ldg(&fL[((nt + 1) * 4 + ks) * 32 + lane]);
            mma16816(acc0, ah[ks], bh0.x, bh0.y);
            mma16816(acc1, ah[ks], bh1.x, bh1.y);
            mma16816(acc0, ah[ks], bl0.x, bl0.y);
            mma16816(acc1, ah[ks], bl1.x, bl1.y);
        }
        #pragma unroll
        for (int p = 0; p < 2; p++) {
            float* acc = p ? acc1 : acc0;
            int ncol = (nt + p) * 8 + 2 * tig;
            float2 bias = *reinterpret_cast<const float2*>(&sBias[ncol]);
            float2 o0 = {acc[0] + bias.x, acc[1] + bias.y};
            float2 o1 = {acc[2] + bias.x, acc[3] + bias.y};
            *reinterpret_cast<float2*>(outbase + (size_t)(m0 + gid)     * GC + ncol) = o0;
            *reinterpret_cast<float2*>(outbase + (size_t)(m0 + gid + 8) * GC + ncol) = o1;
        }
    }
}

// ---------------- Phase B: tensor-core GRU with [h_hi; h_lo] m-packing (r12 winner) ----
static constexpr int OFF_BGL  = 0;        // uint2[32nt][8ks][32ln] 65536 B
static constexpr int OFF_BCL  = 65536;    // uint2[16][8][32]       32768 B
static constexpr int OFF_A    = 98304;    // u32[8ks][32ln][4]      4096 B
static constexpr int OFF_R    = 102400;
static constexpr int OFF_H    = 106496;   // f32[8][132]            4224 B
static constexpr int OFF_U    = 110720;
static constexpr int OFF_META = 114944;
static constexpr int G_SMEM   = 115072;
#define HS 132

__global__ void __launch_bounds__(512, 1) gru_mma_kernel(
    const int* __restrict__ seq_lens,
    const float* __restrict__ gk, const float* __restrict__ ck,
    float* __restrict__ out)
{
    extern __shared__ char dynsmem[];
    uint2* sBgL = (uint2*)(dynsmem + OFF_BGL);
    uint2* sBcL = (uint2*)(dynsmem + OFF_BCL);
    uint32_t* sA = (uint32_t*)(dynsmem + OFF_A);
    uint32_t* sR = (uint32_t*)(dynsmem + OFF_R);
    float* sH = (float*)(dynsmem + OFF_H);
    float* sU = (float*)(dynsmem + OFF_U);
    int* srow = (int*)(dynsmem + OFF_META);
    int* slen = srow + 8;

    int tid = threadIdx.x;
    int wid = tid >> 5, lane = tid & 31;
    int gid = lane >> 2, tig = lane & 3;
    int nt0 = 2 * wid, nt1 = nt0 + 1;

    // weight-lo fragments -> smem
    for (int idx = tid; idx < 32 * 8 * 32; idx += 512) {
        uint2 lo;
        frag_make(gk, 256, idx >> 8, (idx >> 5) & 7, idx & 31, lo);
        sBgL[idx] = lo;
    }
    for (int idx = tid; idx < 16 * 8 * 32; idx += 512) {
        uint2 lo;
        frag_make(ck, 128, idx >> 8, (idx >> 5) & 7, idx & 31, lo);
        sBcL[idx] = lo;
    }
    // weight-hi fragments -> registers
    uint2 BgH0[8], BgH1[8], BcH[8];
    #pragma unroll
    for (int ks = 0; ks < 8; ks++) {
        uint2 dump;
        BgH0[ks] = frag_make(gk, 256, nt0, ks, lane, dump);
        BgH1[ks] = frag_make(gk, 256, nt1, ks, lane, dump);
        BcH[ks]  = frag_make(ck, 128, wid, ks, lane, dump);
    }
    // zero state
    for (int i = tid; i < 1024; i += 512) { sA[i] = 0u; sR[i] = 0u; }
    for (int i = tid; i < 8 * HS; i += 512) { sH[i] = 0.0f; sU[i] = 0.0f; }
    if (tid < 8) {
        int row = g_order[blockIdx.x * 8 + tid];
        srow[tid] = row;
        slen[tid] = seq_lens[row];
    }
    __syncthreads();

    int maxlen = slen[0];
    int mylen  = slen[gid];
    int myxoff = srow[gid] * (T_ * GC);
    int cA0 = 16 * wid + 2 * tig;
    int cA1 = cA0 + 8;
    int j0  = 8 * wid + 2 * tig;
    bool isR = (wid < 8);
    int rhOff = (wid * 32 + lane) * 4;
    int ahOff = ((j0 >> 4) * 32 + lane) * 4 + ((wid & 1) ? 2 : 0);

    // preload x-projections for t = 0
    float2 xg0 = make_float2(0.f, 0.f), xg1 = make_float2(0.f, 0.f), xc = make_float2(0.f, 0.f);
    if (0 < mylen) {
        xg0 = *reinterpret_cast<const float2*>(&g_xproj[myxoff + cA0]);
        xg1 = *reinterpret_cast<const float2*>(&g_xproj[myxoff + cA1]);
        xc  = *reinterpret_cast<const float2*>(&g_xproj[myxoff + 256 + j0]);
    }

    for (int t = 0; t < maxlen; t++) {
        float2 xg0n = make_float2(0.f, 0.f), xg1n = make_float2(0.f, 0.f);
        float2 xcn  = make_float2(0.f, 0.f);
        if (t + 1 < mylen) {
            int bn = myxoff + (t + 1) * GC;
            xg0n = *reinterpret_cast<const float2*>(&g_xproj[bn + cA0]);
            xg1n = *reinterpret_cast<const float2*>(&g_xproj[bn + cA1]);
            xcn  = *reinterpret_cast<const float2*>(&g_xproj[bn + 256 + j0]);
        }
        bool act = (t < mylen);

        // ---- gate MMA: A=[h_hi;h_lo], 4 independent 8-deep chains ----
        float d1a[4] = {0.f,0.f,0.f,0.f}, d1b[4] = {0.f,0.f,0.f,0.f};
        float d2a[4] = {0.f,0.f,0.f,0.f}, d2b[4] = {0.f,0.f,0.f,0.f};
        #pragma unroll
        for (int ks = 0; ks < 8; ks++) {
            uint4 a4 = *reinterpret_cast<const uint4*>(&sA[(ks * 32 + lane) * 4]);
            uint2 bl0 = sBgL[(nt0 * 8 + ks) * 32 + lane];
            uint2 bl1 = sBgL[(nt1 * 8 + ks) * 32 + lane];
            const uint32_t* a = reinterpret_cast<const uint32_t*>(&a4);
            mma16816(d1a, a, BgH0[ks].x, BgH0[ks].y);
            mma16816(d1b, a, BgH1[ks].x, BgH1[ks].y);
            mma16816(d2a, a, bl0.x, bl0.y);
            mma16816(d2b, a, bl1.x, bl1.y);
        }
        float s0 = sigmoidf_(d1a[0] + d1a[2] + d2a[0] + d2a[2] + xg0.x);
        float s1 = sigmoidf_(d1a[1] + d1a[3] + d2a[1] + d2a[3] + xg0.y);
        float s2 = sigmoidf_(d1b[0] + d1b[2] + d2b[0] + d2b[2] + xg1.x);
        float s3 = sigmoidf_(d1b[1] + d1b[3] + d2b[1] + d2b[3] + xg1.y);
        if (isR) {
            float2 h01 = *reinterpret_cast<const float2*>(&sH[gid * HS + cA0]);
            float2 h23 = *reinterpret_cast<const float2*>(&sH[gid * HS + cA1]);
            uint32_t lo;
            uint32_t hi = split_pack(s0 * h01.x, s1 * h01.y, lo);
            sR[rhOff]     = hi; sR[rhOff + 1] = lo;
            hi = split_pack(s2 * h23.x, s3 * h23.y, lo);
            sR[rhOff + 2] = hi; sR[rhOff + 3] = lo;
        } else {
            *reinterpret_cast<float2*>(&sU[gid * HS + cA0 - 128]) = make_float2(s0, s1);
            *reinterpret_cast<float2*>(&sU[gid * HS + cA1 - 128]) = make_float2(s2, s3);
        }
        __syncthreads();

        float2 uu   = *reinterpret_cast<const float2*>(&sU[gid * HS + j0]);
        float2 hold = *reinterpret_cast<const float2*>(&sH[gid * HS + j0]);

        // ---- cand MMA: A=[rh_hi;rh_lo], 2 independent 8-deep chains ----
        float c1[4] = {0.f,0.f,0.f,0.f}, c2[4] = {0.f,0.f,0.f,0.f};
        #pragma unroll
        for (int ks = 0; ks < 8; ks++) {
            uint4 a4 = *reinterpret_cast<const uint4*>(&sR[(ks * 32 + lane) * 4]);
            uint2 bl = sBcL[(wid * 8 + ks) * 32 + lane];
            const uint32_t* a = reinterpret_cast<const uint32_t*>(&a4);
            mma16816(c1, a, BcH[ks].x, BcH[ks].y);
            mma16816(c2, a, bl.x, bl.y);
        }

        // ---- update (this thread owns h[gid][j0..j0+1]) ----
        if (act) {
            float cc0 = tanhf_(c1[0] + c1[2] + c2[0] + c2[2] + xc.x);
            float cc1 = tanhf_(c1[1] + c1[3] + c2[1] + c2[3] + xc.y);
            float hn0 = uu.x * hold.x + (1.0f - uu.x) * cc0;
            float hn1 = uu.y * hold.y + (1.0f - uu.y) * cc1;
            *reinterpret_cast<float2*>(&sH[gid * HS + j0]) = make_float2(hn0, hn1);
            uint32_t lo;
            uint32_t hi = split_pack(hn0, hn1, lo);
            sA[ahOff]     = hi;
            sA[ahOff + 1] = lo;
        }
        __syncthreads();

        xg0 = xg0n; xg1 = xg1n; xc = xcn;
    }

    float2 hv = *reinterpret_cast<const float2*>(&sH[gid * HS + j0]);
    *reinterpret_cast<float2*>(&out[(size_t)srow[gid] * H_ + j0]) = hv;
}

// ---------------- launch ----------------
extern "C" void kernel_launch(void* const* d_in, const int* in_sizes, int n_in,
                              void* d_out, int out_size) {
    const int*   item_his = (const int*)  d_in[0];
    const int*   seq_lens = (const int*)  d_in[1];
    const float* emb      = (const float*)d_in[2];
    const float* gk       = (const float*)d_in[3];
    const float* gb       = (const float*)d_in[4];
    const float* ck       = (const float*)d_in[5];
    const float* cb       = (const float*)d_in[6];
    float*       out      = (float*)d_out;

    cudaFuncSetAttribute(xproj_mma_kernel, cudaFuncAttributeMaxDynamicSharedMemorySize, PA_SMEM);
    cudaFuncSetAttribute(gru_mma_kernel,   cudaFuncAttributeMaxDynamicSharedMemorySize, G_SMEM);

    setup_kernel<<<2, 256>>>(seq_lens, gk, ck);
    xproj_mma_kernel<<<B_ * 2, 256, PA_SMEM>>>(item_his, seq_lens, emb, gb, cb);
    gru_mma_kernel<<<B_ / 8, 512, G_SMEM>>>(seq_lens, gk, ck, out);
}

// round 15
// speedup vs baseline: 2.9936x; 1.1838x over previous
#include <cuda_runtime.h>
#include <cuda_fp16.h>
#include <cstdint>

#define B_    1024
#define T_    256
#define D_    64
#define H_    128
#define GC    384

__device__ __half g_xproj[(size_t)B_ * T_ * GC];   // fp16 x-projections (~201MB)
__device__ int    g_order[B_];
__device__ uint2  g_bfx[6144];    // Phase-A W fragments (fp16), [48nt][4ks][32ln]

__device__ __forceinline__ float sigmoidf_(float x) {
    return __fdividef(1.0f, 1.0f + __expf(-x));
}
__device__ __forceinline__ float tanhf_(float x) {
    return 1.0f - __fdividef(2.0f, __expf(2.0f * x) + 1.0f);
}

// ---------------- warp-level fp16 MMA (f32 accum) ----------------
__device__ __forceinline__ void mma16816(float* d, const uint32_t* a, uint32_t b0, uint32_t b1) {
    asm volatile(
        "mma.sync.aligned.m16n8k16.row.col.f32.f16.f16.f32 "
        "{%0,%1,%2,%3}, {%4,%5,%6,%7}, {%8,%9}, {%0,%1,%2,%3};"
        : "+f"(d[0]), "+f"(d[1]), "+f"(d[2]), "+f"(d[3])
        : "r"(a[0]), "r"(a[1]), "r"(a[2]), "r"(a[3]), "r"(b0), "r"(b1));
}

__device__ __forceinline__ uint32_t pack_h2(float x, float y) {
    __half2 h = __floats2half2_rn(x, y);
    return *reinterpret_cast<uint32_t*>(&h);
}
// fp16 hi/lo split of a float pair
__device__ __forceinline__ uint32_t split_pack_h(float x, float y, uint32_t& lo) {
    __half hx = __float2half_rn(x), hy = __float2half_rn(y);
    float rx = x - __half2float(hx), ry = y - __half2float(hy);
    __half2 hp = __halves2half2(hx, hy);
    __half2 lp = __floats2half2_rn(rx, ry);
    lo = *reinterpret_cast<uint32_t*>(&lp);
    return *reinterpret_cast<uint32_t*>(&hp);
}

// B-fragment builder (fp16 hi only) for RECURRENT W rows (64+k)
__device__ __forceinline__ uint2 frag_make(const float* W, int ldn, int nt, int ks, int ln) {
    int g = ln >> 2, tg = ln & 3;
    int n = 8 * nt + g, k0 = 16 * ks + 2 * tg;
    uint32_t h0 = pack_h2(W[(64 + k0)     * ldn + n], W[(64 + k0 + 1) * ldn + n]);
    uint32_t h1 = pack_h2(W[(64 + k0 + 8) * ldn + n], W[(64 + k0 + 9) * ldn + n]);
    return make_uint2(h0, h1);
}

// B-fragment builder (fp16) for X-PART W rows (0..63), combined 384-col space
__device__ __forceinline__ uint2 frag_make_x(const float* gkp, const float* ckp,
                                             int nt, int ks, int ln) {
    int g = ln >> 2, tg = ln & 3;
    int n = 8 * nt + g, k0 = 16 * ks + 2 * tg;
    float w00, w01, w10, w11;
    if (n < 256) {
        w00 = gkp[k0 * 256 + n];       w01 = gkp[(k0 + 1) * 256 + n];
        w10 = gkp[(k0 + 8) * 256 + n]; w11 = gkp[(k0 + 9) * 256 + n];
    } else {
        int m = n - 256;
        w00 = ckp[k0 * 128 + m];       w01 = ckp[(k0 + 1) * 128 + m];
        w10 = ckp[(k0 + 8) * 128 + m]; w11 = ckp[(k0 + 9) * 128 + m];
    }
    return make_uint2(pack_h2(w00, w01), pack_h2(w10, w11));
}

// ---------------- setup: sort (block 0) + Phase-A weight frag build (block 1) ----------
__global__ void setup_kernel(const int* __restrict__ seq_lens,
                             const float* __restrict__ gk, const float* __restrict__ ck) {
    int tid = threadIdx.x;
    if (blockIdx.x == 0) {
        __shared__ int hist[T_];
        __shared__ int offs[T_];
        for (int i = tid; i < T_; i += 256) hist[i] = 0;
        __syncthreads();
        for (int i = tid; i < B_; i += 256) atomicAdd(&hist[T_ - 1 - seq_lens[i]], 1);
        __syncthreads();
        if (tid == 0) { int s = 0; for (int k = 0; k < T_; k++) { offs[k] = s; s += hist[k]; } }
        __syncthreads();
        for (int i = tid; i < T_; i += 256) hist[i] = 0;
        __syncthreads();
        for (int i = tid; i < B_; i += 256) {
            int key = T_ - 1 - seq_lens[i];
            g_order[offs[key] + atomicAdd(&hist[key], 1)] = i;
        }
    } else {
        for (int idx = tid; idx < 6144; idx += 256) {
            int nt = idx >> 7, ks = (idx >> 5) & 3, ln = idx & 31;
            g_bfx[idx] = frag_make_x(gk, ck, nt, ks, ln);
        }
    }
}

// ---------------- Phase A v4: fp16 single pass, per-warp len skip ----------------
static constexpr int BIAS_OFF = 0;        // 384 f32
static constexpr int AH_OFF   = 1536;     // [128][72] fp16
static constexpr int PA_SMEM  = 20096;
#define SA 72

__global__ void __launch_bounds__(256, 4) xproj_mma_kernel(
    const int* __restrict__ item_his, const int* __restrict__ seq_lens,
    const float* __restrict__ emb,
    const float* __restrict__ gb, const float* __restrict__ cb)
{
    extern __shared__ char dynsmem[];
    float*  sBias = (float*)(dynsmem + BIAS_OFF);
    __half* sAh   = (__half*)(dynsmem + AH_OFF);

    int b  = blockIdx.x >> 1;
    int t0 = (blockIdx.x & 1) << 7;
    int len = seq_lens[b];
    if (t0 >= len) return;
    int mrows = len - t0;

    int tid = threadIdx.x;

    for (int i = tid; i < GC; i += 256) sBias[i] = (i < 256) ? gb[i] : cb[i - 256];

    // A gather: 2 threads per row, each 32 cols; plain fp16
    {
        int r = tid >> 1, half = tid & 1;
        int item = item_his[b * T_ + t0 + r];
        const float4* e4 = reinterpret_cast<const float4*>(emb + (size_t)item * D_ + half * 32);
        #pragma unroll
        for (int q = 0; q < 8; q += 2) {
            float4 v0 = e4[q], v1 = e4[q + 1];
            uint32_t p[4];
            p[0] = pack_h2(v0.x, v0.y);
            p[1] = pack_h2(v0.z, v0.w);
            p[2] = pack_h2(v1.x, v1.y);
            p[3] = pack_h2(v1.z, v1.w);
            int c0 = half * 32 + q * 4;
            *reinterpret_cast<uint4*>(&sAh[r * SA + c0]) = *reinterpret_cast<uint4*>(p);
        }
    }
    __syncthreads();

    int wid = tid >> 5, lane = tid & 31;
    int gid = lane >> 2, tig = lane & 3;
    int m0 = wid * 16;

    if (m0 >= mrows) return;   // whole m-tile past sequence end

    uint32_t ah[4][4];
    #pragma unroll
    for (int ks = 0; ks < 4; ks++) {
        int c = ks * 16 + 2 * tig;
        ah[ks][0] = *reinterpret_cast<const uint32_t*>(&sAh[(m0+gid)   * SA + c]);
        ah[ks][1] = *reinterpret_cast<const uint32_t*>(&sAh[(m0+gid+8) * SA + c]);
        ah[ks][2] = *reinterpret_cast<const uint32_t*>(&sAh[(m0+gid)   * SA + c + 8]);
        ah[ks][3] = *reinterpret_cast<const uint32_t*>(&sAh[(m0+gid+8) * SA + c + 8]);
    }

    __half* outbase = g_xproj + ((size_t)b * T_ + t0) * GC;
    const uint2* __restrict__ fH = g_bfx;

    for (int nt = 0; nt < 48; nt += 2) {
        float acc0[4] = {0.f, 0.f, 0.f, 0.f};
        float acc1[4] = {0.f, 0.f, 0.f, 0.f};
        #pragma unroll
        for (int ks = 0; ks < 4; ks++) {
            uint2 bh0 = __ldg(&fH[(nt       * 4 + ks) * 32 + lane]);
            uint2 bh1 = __ldg(&fH[((nt + 1) * 4 + ks) * 32 + lane]);
            mma16816(acc0, ah[ks], bh0.x, bh0.y);
            mma16816(acc1, ah[ks], bh1.x, bh1.y);
        }
        #pragma unroll
        for (int p = 0; p < 2; p++) {
            float* acc = p ? acc1 : acc0;
            int ncol = (nt + p) * 8 + 2 * tig;
            float2 bias = *reinterpret_cast<const float2*>(&sBias[ncol]);
            uint32_t o0 = pack_h2(acc[0] + bias.x, acc[1] + bias.y);
            uint32_t o1 = pack_h2(acc[2] + bias.x, acc[3] + bias.y);
            *reinterpret_cast<uint32_t*>(&outbase[(size_t)(m0 + gid)     * GC + ncol]) = o0;
            *reinterpret_cast<uint32_t*>(&outbase[(size_t)(m0 + gid + 8) * GC + ncol]) = o1;
        }
    }
}

// ---------------- Phase B: fp16 single-pass tensor-core GRU ----------------
// 128 CTAs x 8 rows, 512 threads. A=[h_hi;h_lo] fp16 m-packed; W_hi fp16 in regs.
static constexpr int OFF_A    = 0;        // u32[8ks][32ln][4]  4096 B
static constexpr int OFF_R    = 4096;
static constexpr int OFF_H    = 8192;     // f32[8][132]        4224 B
static constexpr int OFF_U    = 12416;
static constexpr int OFF_META = 16640;
static constexpr int G_SMEM   = 16768;
#define HS 132

__global__ void __launch_bounds__(512, 1) gru_mma_kernel(
    const int* __restrict__ seq_lens,
    const float* __restrict__ gk, const float* __restrict__ ck,
    float* __restrict__ out)
{
    extern __shared__ char dynsmem[];
    uint32_t* sA = (uint32_t*)(dynsmem + OFF_A);
    uint32_t* sR = (uint32_t*)(dynsmem + OFF_R);
    float* sH = (float*)(dynsmem + OFF_H);
    float* sU = (float*)(dynsmem + OFF_U);
    int* srow = (int*)(dynsmem + OFF_META);
    int* slen = srow + 8;

    int tid = threadIdx.x;
    int wid = tid >> 5, lane = tid & 31;
    int gid = lane >> 2, tig = lane & 3;
    int nt0 = 2 * wid, nt1 = nt0 + 1;

    // weight fragments (fp16) -> registers
    uint2 BgH0[8], BgH1[8], BcH[8];
    #pragma unroll
    for (int ks = 0; ks < 8; ks++) {
        BgH0[ks] = frag_make(gk, 256, nt0, ks, lane);
        BgH1[ks] = frag_make(gk, 256, nt1, ks, lane);
        BcH[ks]  = frag_make(ck, 128, wid, ks, lane);
    }
    // zero state
    for (int i = tid; i < 1024; i += 512) { sA[i] = 0u; sR[i] = 0u; }
    for (int i = tid; i < 8 * HS; i += 512) { sH[i] = 0.0f; sU[i] = 0.0f; }
    if (tid < 8) {
        int row = g_order[blockIdx.x * 8 + tid];
        srow[tid] = row;
        slen[tid] = seq_lens[row];
    }
    __syncthreads();

    int maxlen = slen[0];
    int mylen  = slen[gid];
    size_t myxoff = (size_t)srow[gid] * (T_ * GC);
    int cA0 = 16 * wid + 2 * tig;
    int cA1 = cA0 + 8;
    int j0  = 8 * wid + 2 * tig;
    bool isR = (wid < 8);
    int rhOff = (wid * 32 + lane) * 4;
    int ahOff = ((j0 >> 4) * 32 + lane) * 4 + ((wid & 1) ? 2 : 0);

    // preload x-projections for t = 0 (fp16 -> f32)
    float2 xg0 = make_float2(0.f, 0.f), xg1 = make_float2(0.f, 0.f), xc = make_float2(0.f, 0.f);
    if (0 < mylen) {
        xg0 = __half22float2(*reinterpret_cast<const __half2*>(&g_xproj[myxoff + cA0]));
        xg1 = __half22float2(*reinterpret_cast<const __half2*>(&g_xproj[myxoff + cA1]));
        xc  = __half22float2(*reinterpret_cast<const __half2*>(&g_xproj[myxoff + 256 + j0]));
    }

    for (int t = 0; t < maxlen; t++) {
        float2 xg0n = make_float2(0.f, 0.f), xg1n = make_float2(0.f, 0.f);
        float2 xcn  = make_float2(0.f, 0.f);
        if (t + 1 < mylen) {
            size_t bn = myxoff + (size_t)(t + 1) * GC;
            xg0n = __half22float2(*reinterpret_cast<const __half2*>(&g_xproj[bn + cA0]));
            xg1n = __half22float2(*reinterpret_cast<const __half2*>(&g_xproj[bn + cA1]));
            xcn  = __half22float2(*reinterpret_cast<const __half2*>(&g_xproj[bn + 256 + j0]));
        }
        bool act = (t < mylen);

        // ---- gate MMA: A=[h_hi;h_lo] fp16, single pass (2 chains x 8 deep) ----
        float d1a[4] = {0.f,0.f,0.f,0.f}, d1b[4] = {0.f,0.f,0.f,0.f};
        #pragma unroll
        for (int ks = 0; ks < 8; ks++) {
            uint4 a4 = *reinterpret_cast<const uint4*>(&sA[(ks * 32 + lane) * 4]);
            const uint32_t* a = reinterpret_cast<const uint32_t*>(&a4);
            mma16816(d1a, a, BgH0[ks].x, BgH0[ks].y);
            mma16816(d1b, a, BgH1[ks].x, BgH1[ks].y);
        }
        float s0 = sigmoidf_(d1a[0] + d1a[2] + xg0.x);
        float s1 = sigmoidf_(d1a[1] + d1a[3] + xg0.y);
        float s2 = sigmoidf_(d1b[0] + d1b[2] + xg1.x);
        float s3 = sigmoidf_(d1b[1] + d1b[3] + xg1.y);
        if (isR) {
            float2 h01 = *reinterpret_cast<const float2*>(&sH[gid * HS + cA0]);
            float2 h23 = *reinterpret_cast<const float2*>(&sH[gid * HS + cA1]);
            uint32_t lo;
            uint32_t hi = split_pack_h(s0 * h01.x, s1 * h01.y, lo);
            sR[rhOff]     = hi; sR[rhOff + 1] = lo;
            hi = split_pack_h(s2 * h23.x, s3 * h23.y, lo);
            sR[rhOff + 2] = hi; sR[rhOff + 3] = lo;
        } else {
            *reinterpret_cast<float2*>(&sU[gid * HS + cA0 - 128]) = make_float2(s0, s1);
            *reinterpret_cast<float2*>(&sU[gid * HS + cA1 - 128]) = make_float2(s2, s3);
        }
        __syncthreads();

        float2 uu   = *reinterpret_cast<const float2*>(&sU[gid * HS + j0]);
        float2 hold = *reinterpret_cast<const float2*>(&sH[gid * HS + j0]);

        // ---- cand MMA: A=[rh_hi;rh_lo] fp16, single pass (1 chain x 8 deep) ----
        float c1[4] = {0.f,0.f,0.f,0.f};
        #pragma unroll
        for (int ks = 0; ks < 8; ks++) {
            uint4 a4 = *reinterpret_cast<const uint4*>(&sR[(ks * 32 + lane) * 4]);
            const uint32_t* a = reinterpret_cast<const uint32_t*>(&a4);
            mma16816(c1, a, BcH[ks].x, BcH[ks].y);
        }

        // ---- update (this thread owns h[gid][j0..j0+1]) ----
        if (act) {
            float cc0 = tanhf_(c1[0] + c1[2] + xc.x);
            float cc1 = tanhf_(c1[1] + c1[3] + xc.y);
            float hn0 = uu.x * hold.x + (1.0f - uu.x) * cc0;
            float hn1 = uu.y * hold.y + (1.0f - uu.y) * cc1;
            *reinterpret_cast<float2*>(&sH[gid * HS + j0]) = make_float2(hn0, hn1);
            uint32_t lo;
            uint32_t hi = split_pack_h(hn0, hn1, lo);
            sA[ahOff]     = hi;   // row gid   (h_hi)
            sA[ahOff + 1] = lo;   // row gid+8 (h_lo)
        }
        __syncthreads();

        xg0 = xg0n; xg1 = xg1n; xc = xcn;
    }

    float2 hv = *reinterpret_cast<const float2*>(&sH[gid * HS + j0]);
    *reinterpret_cast<float2*>(&out[(size_t)srow[gid] * H_ + j0]) = hv;
}

// ---------------- launch ----------------
extern "C" void kernel_launch(void* const* d_in, const int* in_sizes, int n_in,
                              void* d_out, int out_size) {
    const int*   item_his = (const int*)  d_in[0];
    const int*   seq_lens = (const int*)  d_in[1];
    const float* emb      = (const float*)d_in[2];
    const float* gk       = (const float*)d_in[3];
    const float* gb       = (const float*)d_in[4];
    const float* ck       = (const float*)d_in[5];
    const float* cb       = (const float*)d_in[6];
    float*       out      = (float*)d_out;

    cudaFuncSetAttribute(xproj_mma_kernel, cudaFuncAttributeMaxDynamicSharedMemorySize, PA_SMEM);
    cudaFuncSetAttribute(gru_mma_kernel,   cudaFuncAttributeMaxDynamicSharedMemorySize, G_SMEM);

    setup_kernel<<<2, 256>>>(seq_lens, gk, ck);
    xproj_mma_kernel<<<B_ * 2, 256, PA_SMEM>>>(item_his, seq_lens, emb, gb, cb);
    gru_mma_kernel<<<B_ / 8, 512, G_SMEM>>>(seq_lens, gk, ck, out);
}